// round 2
// baseline (speedup 1.0000x reference)
#include <cuda_runtime.h>
#include <math.h>

#define NN 50000
#define EE 1600000

// ---------------- device scratch (static: no allocs allowed) ----------------
__device__ float g_f[NN * 128];      // projected features of current layer
__device__ float g_h1[NN * 128];     // layer0 output / layer1 input+residual
__device__ float g_h2[NN * 128];     // layer1 output / layer2 input
__device__ float g_res2[NN * 64];    // linear residual for layer2
__device__ float g_el[NN * 8];
__device__ float g_er[NN * 8];
__device__ float g_sinv[NN * 8];
__device__ float g_ex[EE * 8];       // per-edge exp(e - max), sorted-by-dst order
__device__ int   g_cnt[NN];
__device__ int   g_rowptr[NN + 1];
__device__ int   g_srcs[EE];         // src node of each edge, sorted by dst

// ---------------- small utility kernels ----------------
__global__ void zero_int_kernel(int* p, int n) {
    int i = blockIdx.x * blockDim.x + threadIdx.x;
    if (i < n) p[i] = 0;
}

__global__ void hist_kernel(const int* __restrict__ dst, int* __restrict__ cnt, int e) {
    int i = blockIdx.x * blockDim.x + threadIdx.x;
    if (i < e) atomicAdd(&cnt[dst[i]], 1);
}

// single-block Hillis-Steele scan over N counts -> rowptr (exclusive, rowptr[0]=0)
__global__ void scan_kernel(const int* __restrict__ cnt, int* __restrict__ rowptr, int n) {
    __shared__ int sm[1024];
    __shared__ int carry;
    int tid = threadIdx.x;
    if (tid == 0) { carry = 0; rowptr[0] = 0; }
    __syncthreads();
    for (int base = 0; base < n; base += 1024) {
        int i = base + tid;
        int v = (i < n) ? cnt[i] : 0;
        sm[tid] = v;
        __syncthreads();
        #pragma unroll
        for (int off = 1; off < 1024; off <<= 1) {
            int t = (tid >= off) ? sm[tid - off] : 0;
            __syncthreads();
            sm[tid] += t;
            __syncthreads();
        }
        if (i < n) rowptr[i + 1] = sm[tid] + carry;
        __syncthreads();
        if (tid == 0) carry += sm[1023];
        __syncthreads();
    }
}

__global__ void scatter_kernel(const int* __restrict__ src, const int* __restrict__ dst,
                               const int* __restrict__ rowptr, int* __restrict__ fill,
                               int* __restrict__ srcs, int e) {
    int i = blockIdx.x * blockDim.x + threadIdx.x;
    if (i < e) {
        int d = dst[i];
        int pos = rowptr[d] + atomicAdd(&fill[d], 1);
        srcs[pos] = src[i];
    }
}

// ---------------- GEMM: F[n, M] = X[n, 128] @ W[128, M] ----------------
template <int M>
__global__ void gemm_kernel(const float* __restrict__ X, const float* __restrict__ W,
                            float* __restrict__ F, int n) {
    constexpr int TPN = M / 4;       // threads per node
    constexpr int NB  = 256 / TPN;   // nodes per block
    __shared__ float hs[NB][128];
    int n0  = blockIdx.x * NB;
    int tid = threadIdx.x;
    for (int idx = tid; idx < NB * 32; idx += 256) {
        int r = idx >> 5, c = idx & 31;
        int node = n0 + r;
        float4 v = make_float4(0.f, 0.f, 0.f, 0.f);
        if (node < n) v = reinterpret_cast<const float4*>(X)[node * 32 + c];
        reinterpret_cast<float4*>(hs[r])[c] = v;
    }
    __syncthreads();
    int ln = tid / TPN;
    int cg = (tid % TPN) * 4;
    int node = n0 + ln;
    if (node >= n) return;
    float4 acc = make_float4(0.f, 0.f, 0.f, 0.f);
    #pragma unroll 8
    for (int k = 0; k < 128; k++) {
        float4 w = *reinterpret_cast<const float4*>(&W[k * M + cg]);
        float h  = hs[ln][k];
        acc.x += h * w.x; acc.y += h * w.y; acc.z += h * w.z; acc.w += h * w.w;
    }
    *reinterpret_cast<float4*>(&F[node * M + cg]) = acc;
}

// ---------------- per-node attention logits: el/er ----------------
template <int H, int D>
__global__ void eler_kernel(const float* __restrict__ F, const float* __restrict__ al,
                            const float* __restrict__ ar, float* __restrict__ EL,
                            float* __restrict__ ER, int n) {
    int idx = blockIdx.x * blockDim.x + threadIdx.x;
    if (idx >= n * H) return;
    int node = idx / H, h = idx % H;
    const float* fr = F + node * H * D + h * D;
    const float* a  = al + h * D;
    const float* r  = ar + h * D;
    float el = 0.f, er = 0.f;
    #pragma unroll
    for (int d = 0; d < D; d += 4) {
        float4 fv = *reinterpret_cast<const float4*>(fr + d);
        float4 av = *reinterpret_cast<const float4*>(a + d);
        float4 rv = *reinterpret_cast<const float4*>(r + d);
        el += fv.x * av.x + fv.y * av.y + fv.z * av.z + fv.w * av.w;
        er += fv.x * rv.x + fv.y * rv.y + fv.z * rv.z + fv.w * rv.w;
    }
    EL[idx] = el;
    ER[idx] = er;
}

// ---------------- edge softmax (warp per dst node, fused max+exp+sum) -------
template <int H>
__device__ __forceinline__ void load_el(float (&e)[H], const float* __restrict__ p) {
    if constexpr (H == 8) {
        float4 a = *reinterpret_cast<const float4*>(p);
        float4 b = *reinterpret_cast<const float4*>(p + 4);
        e[0] = a.x; e[1] = a.y; e[2] = a.z; e[3] = a.w;
        e[4] = b.x; e[5] = b.y; e[6] = b.z; e[7] = b.w;
    } else {
        e[0] = p[0];
    }
}

template <int H>
__global__ void softmax_kernel(const float* __restrict__ EL, const float* __restrict__ ER,
                               const int* __restrict__ rowptr, const int* __restrict__ srcs,
                               float* __restrict__ EX, float* __restrict__ SINV, int n) {
    int gw = (blockIdx.x * blockDim.x + threadIdx.x) >> 5;
    if (gw >= n) return;
    int lane = threadIdx.x & 31;
    float erl[H];
    #pragma unroll
    for (int h = 0; h < H; h++) erl[h] = ER[gw * H + h];
    int beg = rowptr[gw], end = rowptr[gw + 1];
    float mx[H];
    #pragma unroll
    for (int h = 0; h < H; h++) mx[h] = -3.4e38f;
    for (int i = beg + lane; i < end; i += 32) {
        int s = srcs[i];
        float e[H];
        load_el<H>(e, EL + s * H);
        #pragma unroll
        for (int h = 0; h < H; h++) {
            float x = e[h] + erl[h];
            x = x > 0.f ? x : 0.2f * x;
            mx[h] = fmaxf(mx[h], x);
        }
    }
    #pragma unroll
    for (int h = 0; h < H; h++)
        #pragma unroll
        for (int o = 16; o; o >>= 1)
            mx[h] = fmaxf(mx[h], __shfl_xor_sync(0xffffffffu, mx[h], o));

    float sm[H];
    #pragma unroll
    for (int h = 0; h < H; h++) sm[h] = 0.f;
    for (int i = beg + lane; i < end; i += 32) {
        int s = srcs[i];
        float e[H];
        load_el<H>(e, EL + s * H);
        float ev[H];
        #pragma unroll
        for (int h = 0; h < H; h++) {
            float x = e[h] + erl[h];
            x = x > 0.f ? x : 0.2f * x;
            ev[h] = __expf(x - mx[h]);
            sm[h] += ev[h];
        }
        if constexpr (H == 8) {
            *reinterpret_cast<float4*>(EX + i * 8)     = make_float4(ev[0], ev[1], ev[2], ev[3]);
            *reinterpret_cast<float4*>(EX + i * 8 + 4) = make_float4(ev[4], ev[5], ev[6], ev[7]);
        } else {
            EX[i] = ev[0];
        }
    }
    #pragma unroll
    for (int h = 0; h < H; h++)
        #pragma unroll
        for (int o = 16; o; o >>= 1)
            sm[h] += __shfl_xor_sync(0xffffffffu, sm[h], o);
    if (lane == 0) {
        #pragma unroll
        for (int h = 0; h < H; h++) SINV[gw * H + h] = 1.0f / sm[h];
    }
}

// ------------- message aggregation + fused epilogue (warp per dst node) -----
template <int H, int D, bool ELU_ACT, bool HAS_RES>
__global__ void agg_kernel(const float* __restrict__ F, const float* __restrict__ EX,
                           const float* __restrict__ SINV, const int* __restrict__ rowptr,
                           const int* __restrict__ srcs, const float* __restrict__ RESP,
                           const float* __restrict__ B, float* __restrict__ OUT, int n) {
    constexpr int HD  = H * D;
    constexpr int VPL = HD / 32;     // 4 (HD=128) or 2 (HD=64)
    int gw = (blockIdx.x * blockDim.x + threadIdx.x) >> 5;
    if (gw >= n) return;
    int lane = threadIdx.x & 31;
    int col  = lane * VPL;
    constexpr int DSHIFT = (D == 16) ? 4 : 6;
    int head = col >> DSHIFT;
    float sinv = SINV[gw * H + head];
    float acc[VPL];
    #pragma unroll
    for (int j = 0; j < VPL; j++) acc[j] = 0.f;
    int beg = rowptr[gw], end = rowptr[gw + 1];
    int i = beg;
    for (; i + 2 <= end; i += 2) {
        int s0 = srcs[i], s1 = srcs[i + 1];
        float a0 = EX[i * H + head] * sinv;
        float a1 = EX[(i + 1) * H + head] * sinv;
        const float* f0 = F + s0 * HD + col;
        const float* f1 = F + s1 * HD + col;
        if constexpr (VPL == 4) {
            float4 v0 = *reinterpret_cast<const float4*>(f0);
            float4 v1 = *reinterpret_cast<const float4*>(f1);
            acc[0] += v0.x * a0 + v1.x * a1;
            acc[1] += v0.y * a0 + v1.y * a1;
            acc[2] += v0.z * a0 + v1.z * a1;
            acc[3] += v0.w * a0 + v1.w * a1;
        } else {
            float2 v0 = *reinterpret_cast<const float2*>(f0);
            float2 v1 = *reinterpret_cast<const float2*>(f1);
            acc[0] += v0.x * a0 + v1.x * a1;
            acc[1] += v0.y * a0 + v1.y * a1;
        }
    }
    if (i < end) {
        int s0 = srcs[i];
        float a0 = EX[i * H + head] * sinv;
        const float* f0 = F + s0 * HD + col;
        if constexpr (VPL == 4) {
            float4 v0 = *reinterpret_cast<const float4*>(f0);
            acc[0] += v0.x * a0; acc[1] += v0.y * a0;
            acc[2] += v0.z * a0; acc[3] += v0.w * a0;
        } else {
            float2 v0 = *reinterpret_cast<const float2*>(f0);
            acc[0] += v0.x * a0; acc[1] += v0.y * a0;
        }
    }
    // epilogue: + residual + bias, optional ELU
    float o[VPL];
    #pragma unroll
    for (int j = 0; j < VPL; j++) {
        float v = acc[j] + B[col + j];
        if constexpr (HAS_RES) v += RESP[gw * HD + col + j];
        if constexpr (ELU_ACT) v = v > 0.f ? v : expm1f(v);
        o[j] = v;
    }
    if constexpr (VPL == 4)
        *reinterpret_cast<float4*>(OUT + gw * HD + col) = make_float4(o[0], o[1], o[2], o[3]);
    else
        *reinterpret_cast<float2*>(OUT + gw * HD + col) = make_float2(o[0], o[1]);
}

// ---------------- launch ----------------
extern "C" void kernel_launch(void* const* d_in, const int* in_sizes, int n_in,
                              void* d_out, int out_size) {
    const float* x     = (const float*)d_in[0];
    const int*   src   = (const int*)d_in[1];
    const int*   dst   = (const int*)d_in[2];
    const float* W0    = (const float*)d_in[3];
    const float* al0   = (const float*)d_in[4];
    const float* ar0   = (const float*)d_in[5];
    const float* b0    = (const float*)d_in[6];
    const float* W1    = (const float*)d_in[7];
    const float* al1   = (const float*)d_in[8];
    const float* ar1   = (const float*)d_in[9];
    const float* b1    = (const float*)d_in[10];
    const float* W2    = (const float*)d_in[11];
    const float* al2   = (const float*)d_in[12];
    const float* ar2   = (const float*)d_in[13];
    const float* b2    = (const float*)d_in[14];
    const float* resW2 = (const float*)d_in[15];
    float* out = (float*)d_out;

    const int n = NN;
    const int e = in_sizes[1];

    void* p;
    cudaGetSymbolAddress(&p, g_f);      float* f_    = (float*)p;
    cudaGetSymbolAddress(&p, g_h1);     float* h1_   = (float*)p;
    cudaGetSymbolAddress(&p, g_h2);     float* h2_   = (float*)p;
    cudaGetSymbolAddress(&p, g_res2);   float* res2_ = (float*)p;
    cudaGetSymbolAddress(&p, g_el);     float* el_   = (float*)p;
    cudaGetSymbolAddress(&p, g_er);     float* er_   = (float*)p;
    cudaGetSymbolAddress(&p, g_sinv);   float* sinv_ = (float*)p;
    cudaGetSymbolAddress(&p, g_ex);     float* ex_   = (float*)p;
    cudaGetSymbolAddress(&p, g_cnt);    int*   cnt_  = (int*)p;
    cudaGetSymbolAddress(&p, g_rowptr); int*   rp_   = (int*)p;
    cudaGetSymbolAddress(&p, g_srcs);   int*   srcs_ = (int*)p;

    const int TB = 256;
    int nb_n  = (n + TB - 1) / TB;
    int nb_e  = (e + TB - 1) / TB;
    int nb_w  = (n + 7) / 8;          // warp-per-node kernels, 8 warps/block
    int nb_nh = (n * 8 + TB - 1) / TB;

    // ---- CSR build (sorted by dst) ----
    zero_int_kernel<<<nb_n, TB>>>(cnt_, n);
    hist_kernel<<<nb_e, TB>>>(dst, cnt_, e);
    scan_kernel<<<1, 1024>>>(cnt_, rp_, n);
    zero_int_kernel<<<nb_n, TB>>>(cnt_, n);
    scatter_kernel<<<nb_e, TB>>>(src, dst, rp_, cnt_, srcs_, e);

    // ---- layer 0: IN=128 -> 8x16, no residual, ELU ----
    gemm_kernel<128><<<(n + 7) / 8, TB>>>(x, W0, f_, n);
    eler_kernel<8, 16><<<nb_nh, TB>>>(f_, al0, ar0, el_, er_, n);
    softmax_kernel<8><<<nb_w, TB>>>(el_, er_, rp_, srcs_, ex_, sinv_, n);
    agg_kernel<8, 16, true, false><<<nb_w, TB>>>(f_, ex_, sinv_, rp_, srcs_,
                                                 nullptr, b0, h1_, n);

    // ---- layer 1: 128 -> 8x16, identity residual, ELU ----
    gemm_kernel<128><<<(n + 7) / 8, TB>>>(h1_, W1, f_, n);
    eler_kernel<8, 16><<<nb_nh, TB>>>(f_, al1, ar1, el_, er_, n);
    softmax_kernel<8><<<nb_w, TB>>>(el_, er_, rp_, srcs_, ex_, sinv_, n);
    agg_kernel<8, 16, true, true><<<nb_w, TB>>>(f_, ex_, sinv_, rp_, srcs_,
                                                h1_, b1, h2_, n);

    // ---- layer 2: 128 -> 1x64, linear residual, no act ----
    gemm_kernel<64><<<(n + 15) / 16, TB>>>(h2_, W2, f_, n);
    gemm_kernel<64><<<(n + 15) / 16, TB>>>(h2_, resW2, res2_, n);
    eler_kernel<1, 64><<<nb_n, TB>>>(f_, al2, ar2, el_, er_, n);
    softmax_kernel<1><<<nb_w, TB>>>(el_, er_, rp_, srcs_, ex_, sinv_, n);
    agg_kernel<1, 64, false, true><<<nb_w, TB>>>(f_, ex_, sinv_, rp_, srcs_,
                                                 res2_, b2, out, n);
}

// round 4
// speedup vs baseline: 1.1275x; 1.1275x over previous
#include <cuda_runtime.h>
#include <math.h>

#define NN 50000
#define EE 1600000

// ---------------- device scratch (static: no allocs allowed) ----------------
__device__ float g_f[NN * 128];      // projected features of current layer
__device__ float g_h1[NN * 128];     // layer0 output / layer1 input+residual
__device__ float g_h2[NN * 128];     // layer1 output / layer2 input
__device__ float g_res2[NN * 64];    // linear residual for layer2
__device__ float g_el[NN * 8];
__device__ float g_er[NN * 8];
__device__ int   g_cnt[NN];
__device__ int   g_rowptr[NN + 1];
__device__ int   g_bsum[64];
__device__ int   g_srcs[EE];         // src node of each edge, sorted by dst

// ---------------- small utility kernels ----------------
__global__ void zero_int_kernel(int* p, int n) {
    int i = blockIdx.x * blockDim.x + threadIdx.x;
    if (i < n) p[i] = 0;
}

__global__ void hist_kernel(const int* __restrict__ dst, int* __restrict__ cnt, int e) {
    int i = blockIdx.x * blockDim.x + threadIdx.x;
    if (i < e) atomicAdd(&cnt[dst[i]], 1);
}

// -------- parallel scan: block-local (1024 elems/block) --------
__global__ void scan_local_kernel(const int* __restrict__ cnt, int* __restrict__ rowptr,
                                  int* __restrict__ bsum, int n) {
    __shared__ int wsum[8];
    int tid = threadIdx.x, lane = tid & 31, wid = tid >> 5;
    int base = blockIdx.x * 1024 + tid * 4;
    int v0 = (base     < n) ? cnt[base]     : 0;
    int v1 = (base + 1 < n) ? cnt[base + 1] : 0;
    int v2 = (base + 2 < n) ? cnt[base + 2] : 0;
    int v3 = (base + 3 < n) ? cnt[base + 3] : 0;
    int s0 = v0, s1 = s0 + v1, s2 = s1 + v2, s3 = s2 + v3;
    int incl = s3;
    #pragma unroll
    for (int off = 1; off < 32; off <<= 1) {
        int t = __shfl_up_sync(0xffffffffu, incl, off);
        if (lane >= off) incl += t;
    }
    if (lane == 31) wsum[wid] = incl;
    __syncthreads();
    if (wid == 0) {
        int w = (lane < 8) ? wsum[lane] : 0;
        #pragma unroll
        for (int off = 1; off < 8; off <<= 1) {
            int t = __shfl_up_sync(0xffffffffu, w, off);
            if (lane >= off) w += t;
        }
        if (lane < 8) wsum[lane] = w;
    }
    __syncthreads();
    int woff = (wid > 0) ? wsum[wid - 1] : 0;
    int excl = incl - s3 + woff;
    if (base     < n) rowptr[base + 1] = excl + s0;
    if (base + 1 < n) rowptr[base + 2] = excl + s1;
    if (base + 2 < n) rowptr[base + 3] = excl + s2;
    if (base + 3 < n) rowptr[base + 4] = excl + s3;
    if (tid == 0) bsum[blockIdx.x] = 0;   // will be overwritten below by last thread
    __syncthreads();
    if (tid == 255) bsum[blockIdx.x] = wsum[7];
}

// exclusive scan over block sums (<= 64 entries), single warp
__global__ void scan_bsum_kernel(int* bsum, int nb) {
    int lane = threadIdx.x;
    int carry = 0;
    for (int base = 0; base < nb; base += 32) {
        int v = (base + lane < nb) ? bsum[base + lane] : 0;
        int incl = v;
        #pragma unroll
        for (int off = 1; off < 32; off <<= 1) {
            int t = __shfl_up_sync(0xffffffffu, incl, off);
            if (lane >= off) incl += t;
        }
        int excl = incl - v + carry;
        if (base + lane < nb) bsum[base + lane] = excl;
        carry += __shfl_sync(0xffffffffu, incl, 31);
    }
}

__global__ void scan_add_kernel(const int* __restrict__ bsum, int* __restrict__ rowptr, int n) {
    int i = blockIdx.x * blockDim.x + threadIdx.x;
    if (i < n) rowptr[i + 1] += bsum[i >> 10];
    if (i == 0) rowptr[0] = 0;
}

__global__ void scatter_kernel(const int* __restrict__ src, const int* __restrict__ dst,
                               const int* __restrict__ rowptr, int* __restrict__ fill,
                               int* __restrict__ srcs, int e) {
    int i = blockIdx.x * blockDim.x + threadIdx.x;
    if (i < e) {
        int d = dst[i];
        int pos = rowptr[d] + atomicAdd(&fill[d], 1);
        srcs[pos] = src[i];
    }
}

// ---------------- GEMM: F[n, M] = X[n, 128] @ W[128, M] ----------------
template <int M>
__global__ void gemm_kernel(const float* __restrict__ X, const float* __restrict__ W,
                            float* __restrict__ F, int n) {
    constexpr int TPN = M / 4;       // threads per node
    constexpr int NB  = 256 / TPN;   // nodes per block
    __shared__ float hs[NB][128];
    int n0  = blockIdx.x * NB;
    int tid = threadIdx.x;
    for (int idx = tid; idx < NB * 32; idx += 256) {
        int r = idx >> 5, c = idx & 31;
        int node = n0 + r;
        float4 v = make_float4(0.f, 0.f, 0.f, 0.f);
        if (node < n) v = reinterpret_cast<const float4*>(X)[node * 32 + c];
        reinterpret_cast<float4*>(hs[r])[c] = v;
    }
    __syncthreads();
    int ln = tid / TPN;
    int cg = (tid % TPN) * 4;
    int node = n0 + ln;
    if (node >= n) return;
    float4 acc = make_float4(0.f, 0.f, 0.f, 0.f);
    #pragma unroll 8
    for (int k = 0; k < 128; k++) {
        float4 w = *reinterpret_cast<const float4*>(&W[k * M + cg]);
        float h  = hs[ln][k];
        acc.x += h * w.x; acc.y += h * w.y; acc.z += h * w.z; acc.w += h * w.w;
    }
    *reinterpret_cast<float4*>(&F[node * M + cg]) = acc;
}

// ---------------- per-node attention logits: el/er ----------------
template <int H, int D>
__global__ void eler_kernel(const float* __restrict__ F, const float* __restrict__ al,
                            const float* __restrict__ ar, float* __restrict__ EL,
                            float* __restrict__ ER, int n) {
    int idx = blockIdx.x * blockDim.x + threadIdx.x;
    if (idx >= n * H) return;
    int node = idx / H, h = idx % H;
    const float* fr = F + node * H * D + h * D;
    const float* a  = al + h * D;
    const float* r  = ar + h * D;
    float el = 0.f, er = 0.f;
    #pragma unroll
    for (int d = 0; d < D; d += 4) {
        float4 fv = *reinterpret_cast<const float4*>(fr + d);
        float4 av = *reinterpret_cast<const float4*>(a + d);
        float4 rv = *reinterpret_cast<const float4*>(r + d);
        el += fv.x * av.x + fv.y * av.y + fv.z * av.z + fv.w * av.w;
        er += fv.x * rv.x + fv.y * rv.y + fv.z * rv.z + fv.w * rv.w;
    }
    EL[idx] = el;
    ER[idx] = er;
}

// ---------- fused edge softmax + aggregation + epilogue (warp/node) ---------
// No max-subtraction (logits are O(1)); no EX scratch — exp recomputed in
// pass B from L1/L2-resident EL/ER.
template <int H, int D, bool ELU_ACT, bool HAS_RES>
__global__ void fused_layer_kernel(const float* __restrict__ F,
                                   const float* __restrict__ EL,
                                   const float* __restrict__ ER,
                                   const int* __restrict__ rowptr,
                                   const int* __restrict__ srcs,
                                   const float* __restrict__ RESP,
                                   const float* __restrict__ B,
                                   float* __restrict__ OUT, int n) {
    constexpr int HD  = H * D;
    constexpr int VPL = HD / 32;     // 4 (HD=128) or 2 (HD=64)
    int gw = (blockIdx.x * blockDim.x + threadIdx.x) >> 5;
    if (gw >= n) return;
    int lane = threadIdx.x & 31;

    float er[H];
    #pragma unroll
    for (int h = 0; h < H; h++) er[h] = ER[gw * H + h];
    int beg = rowptr[gw], end = rowptr[gw + 1];

    // ---- pass A: denominator sum of exp(leaky(el+er)) per head (lane-strided)
    float sm[H];
    #pragma unroll
    for (int h = 0; h < H; h++) sm[h] = 0.f;
    for (int i = beg + lane; i < end; i += 32) {
        int s = srcs[i];
        if constexpr (H == 8) {
            float4 a = *reinterpret_cast<const float4*>(EL + s * 8);
            float4 b = *reinterpret_cast<const float4*>(EL + s * 8 + 4);
            float e[8] = {a.x, a.y, a.z, a.w, b.x, b.y, b.z, b.w};
            #pragma unroll
            for (int h = 0; h < 8; h++) {
                float x = e[h] + er[h];
                x = x > 0.f ? x : 0.2f * x;
                sm[h] += __expf(x);
            }
        } else {
            float x = EL[s] + er[0];
            x = x > 0.f ? x : 0.2f * x;
            sm[0] += __expf(x);
        }
    }
    #pragma unroll
    for (int h = 0; h < H; h++)
        #pragma unroll
        for (int o = 16; o; o >>= 1)
            sm[h] += __shfl_xor_sync(0xffffffffu, sm[h], o);

    // ---- pass B: weighted feature gather (whole warp walks each edge) ----
    constexpr int DSHIFT = (D == 16) ? 4 : 6;
    int col  = lane * VPL;
    int head = col >> DSHIFT;
    float sinv = 1.0f / sm[head];
    float erh  = er[head];
    float acc[VPL];
    #pragma unroll
    for (int j = 0; j < VPL; j++) acc[j] = 0.f;

    auto alpha_of = [&](int s) -> float {
        float x = EL[s * H + head] + erh;
        x = x > 0.f ? x : 0.2f * x;
        return __expf(x) * sinv;
    };

    int i = beg;
    for (; i + 4 <= end; i += 4) {
        int s0 = srcs[i], s1 = srcs[i + 1], s2 = srcs[i + 2], s3 = srcs[i + 3];
        float a0 = alpha_of(s0), a1 = alpha_of(s1), a2 = alpha_of(s2), a3 = alpha_of(s3);
        if constexpr (VPL == 4) {
            float4 v0 = *reinterpret_cast<const float4*>(F + s0 * HD + col);
            float4 v1 = *reinterpret_cast<const float4*>(F + s1 * HD + col);
            float4 v2 = *reinterpret_cast<const float4*>(F + s2 * HD + col);
            float4 v3 = *reinterpret_cast<const float4*>(F + s3 * HD + col);
            acc[0] += v0.x * a0 + v1.x * a1 + v2.x * a2 + v3.x * a3;
            acc[1] += v0.y * a0 + v1.y * a1 + v2.y * a2 + v3.y * a3;
            acc[2] += v0.z * a0 + v1.z * a1 + v2.z * a2 + v3.z * a3;
            acc[3] += v0.w * a0 + v1.w * a1 + v2.w * a2 + v3.w * a3;
        } else {
            float2 v0 = *reinterpret_cast<const float2*>(F + s0 * HD + col);
            float2 v1 = *reinterpret_cast<const float2*>(F + s1 * HD + col);
            float2 v2 = *reinterpret_cast<const float2*>(F + s2 * HD + col);
            float2 v3 = *reinterpret_cast<const float2*>(F + s3 * HD + col);
            acc[0] += v0.x * a0 + v1.x * a1 + v2.x * a2 + v3.x * a3;
            acc[1] += v0.y * a0 + v1.y * a1 + v2.y * a2 + v3.y * a3;
        }
    }
    for (; i < end; i++) {
        int s0 = srcs[i];
        float a0 = alpha_of(s0);
        if constexpr (VPL == 4) {
            float4 v0 = *reinterpret_cast<const float4*>(F + s0 * HD + col);
            acc[0] += v0.x * a0; acc[1] += v0.y * a0;
            acc[2] += v0.z * a0; acc[3] += v0.w * a0;
        } else {
            float2 v0 = *reinterpret_cast<const float2*>(F + s0 * HD + col);
            acc[0] += v0.x * a0; acc[1] += v0.y * a0;
        }
    }

    // ---- epilogue: + residual + bias, optional ELU ----
    float o[VPL];
    #pragma unroll
    for (int j = 0; j < VPL; j++) {
        float v = acc[j] + B[col + j];
        if constexpr (HAS_RES) v += RESP[gw * HD + col + j];
        if constexpr (ELU_ACT) v = v > 0.f ? v : expm1f(v);
        o[j] = v;
    }
    if constexpr (VPL == 4)
        *reinterpret_cast<float4*>(OUT + gw * HD + col) = make_float4(o[0], o[1], o[2], o[3]);
    else
        *reinterpret_cast<float2*>(OUT + gw * HD + col) = make_float2(o[0], o[1]);
}

// ---------------- launch ----------------
extern "C" void kernel_launch(void* const* d_in, const int* in_sizes, int n_in,
                              void* d_out, int out_size) {
    const float* x     = (const float*)d_in[0];
    const int*   src   = (const int*)d_in[1];
    const int*   dst   = (const int*)d_in[2];
    const float* W0    = (const float*)d_in[3];
    const float* al0   = (const float*)d_in[4];
    const float* ar0   = (const float*)d_in[5];
    const float* b0    = (const float*)d_in[6];
    const float* W1    = (const float*)d_in[7];
    const float* al1   = (const float*)d_in[8];
    const float* ar1   = (const float*)d_in[9];
    const float* b1    = (const float*)d_in[10];
    const float* W2    = (const float*)d_in[11];
    const float* al2   = (const float*)d_in[12];
    const float* ar2   = (const float*)d_in[13];
    const float* b2    = (const float*)d_in[14];
    const float* resW2 = (const float*)d_in[15];
    float* out = (float*)d_out;

    const int n = NN;
    const int e = in_sizes[1];

    void* p;
    cudaGetSymbolAddress(&p, g_f);      float* f_    = (float*)p;
    cudaGetSymbolAddress(&p, g_h1);     float* h1_   = (float*)p;
    cudaGetSymbolAddress(&p, g_h2);     float* h2_   = (float*)p;
    cudaGetSymbolAddress(&p, g_res2);   float* res2_ = (float*)p;
    cudaGetSymbolAddress(&p, g_el);     float* el_   = (float*)p;
    cudaGetSymbolAddress(&p, g_er);     float* er_   = (float*)p;
    cudaGetSymbolAddress(&p, g_cnt);    int*   cnt_  = (int*)p;
    cudaGetSymbolAddress(&p, g_rowptr); int*   rp_   = (int*)p;
    cudaGetSymbolAddress(&p, g_bsum);   int*   bs_   = (int*)p;
    cudaGetSymbolAddress(&p, g_srcs);   int*   srcs_ = (int*)p;

    const int TB = 256;
    int nb_n   = (n + TB - 1) / TB;
    int nb_e   = (e + TB - 1) / TB;
    int nb_w   = (n + 7) / 8;          // warp-per-node kernels, 8 warps/block
    int nb_nh  = (n * 8 + TB - 1) / TB;
    int nb_sc  = (n + 1023) / 1024;    // scan blocks

    // ---- CSR build (sorted by dst) ----
    zero_int_kernel<<<nb_n, TB>>>(cnt_, n);
    hist_kernel<<<nb_e, TB>>>(dst, cnt_, e);
    scan_local_kernel<<<nb_sc, 256>>>(cnt_, rp_, bs_, n);
    scan_bsum_kernel<<<1, 32>>>(bs_, nb_sc);
    scan_add_kernel<<<nb_n, TB>>>(bs_, rp_, n);
    zero_int_kernel<<<nb_n, TB>>>(cnt_, n);
    scatter_kernel<<<nb_e, TB>>>(src, dst, rp_, cnt_, srcs_, e);

    // ---- layer 0: IN=128 -> 8x16, no residual, ELU ----
    gemm_kernel<128><<<(n + 7) / 8, TB>>>(x, W0, f_, n);
    eler_kernel<8, 16><<<nb_nh, TB>>>(f_, al0, ar0, el_, er_, n);
    fused_layer_kernel<8, 16, true, false><<<nb_w, TB>>>(f_, el_, er_, rp_, srcs_,
                                                         nullptr, b0, h1_, n);

    // ---- layer 1: 128 -> 8x16, identity residual, ELU ----
    gemm_kernel<128><<<(n + 7) / 8, TB>>>(h1_, W1, f_, n);
    eler_kernel<8, 16><<<nb_nh, TB>>>(f_, al1, ar1, el_, er_, n);
    fused_layer_kernel<8, 16, true, true><<<nb_w, TB>>>(f_, el_, er_, rp_, srcs_,
                                                        h1_, b1, h2_, n);

    // ---- layer 2: 128 -> 1x64, linear residual, no act ----
    gemm_kernel<64><<<(n + 15) / 16, TB>>>(h2_, W2, f_, n);
    gemm_kernel<64><<<(n + 15) / 16, TB>>>(h2_, resW2, res2_, n);
    eler_kernel<1, 64><<<nb_n, TB>>>(f_, al2, ar2, el_, er_, n);
    fused_layer_kernel<1, 64, false, true><<<nb_w, TB>>>(f_, el_, er_, rp_, srcs_,
                                                         res2_, b2, out, n);
}

// round 5
// speedup vs baseline: 1.5063x; 1.3359x over previous
#include <cuda_runtime.h>
#include <math.h>

#define NN 50000
#define EE 1600000

// ---------------- device scratch (static: no allocs allowed) ----------------
__device__ float g_f[NN * 128];      // projected features of current layer
__device__ float g_h1[NN * 128];     // layer0 output / layer1 input+residual
__device__ float g_h2[NN * 128];     // layer1 output / layer2 input
__device__ float g_res2[NN * 64];    // linear residual for layer2
__device__ float g_el[NN * 8];
__device__ float g_er[NN * 8];
__device__ int   g_cnt[NN];
__device__ int   g_rowptr[NN + 1];
__device__ int   g_bsum[64];
__device__ int   g_srcs[EE];         // src node of each edge, sorted by dst

// ---------------- packed f32x2 helpers ----------------
__device__ __forceinline__ unsigned long long pack2(float lo, float hi) {
    unsigned long long r;
    asm("mov.b64 %0, {%1, %2};" : "=l"(r) : "f"(lo), "f"(hi));
    return r;
}
__device__ __forceinline__ void unpack2(unsigned long long v, float& lo, float& hi) {
    asm("mov.b64 {%0, %1}, %2;" : "=f"(lo), "=f"(hi) : "l"(v));
}
__device__ __forceinline__ unsigned long long fma2(unsigned long long a,
                                                   unsigned long long b,
                                                   unsigned long long c) {
    unsigned long long r;
    asm("fma.rn.f32x2 %0, %1, %2, %3;" : "=l"(r) : "l"(a), "l"(b), "l"(c));
    return r;
}

// ---------------- small utility kernels ----------------
__global__ void zero_int_kernel(int* p, int n) {
    int i = blockIdx.x * blockDim.x + threadIdx.x;
    if (i < n) p[i] = 0;
}

__global__ void hist_kernel(const int* __restrict__ dst, int* __restrict__ cnt, int e) {
    int i = blockIdx.x * blockDim.x + threadIdx.x;
    if (i < e) atomicAdd(&cnt[dst[i]], 1);
}

// -------- parallel scan: block-local (1024 elems/block) --------
__global__ void scan_local_kernel(const int* __restrict__ cnt, int* __restrict__ rowptr,
                                  int* __restrict__ bsum, int n) {
    __shared__ int wsum[8];
    int tid = threadIdx.x, lane = tid & 31, wid = tid >> 5;
    int base = blockIdx.x * 1024 + tid * 4;
    int v0 = (base     < n) ? cnt[base]     : 0;
    int v1 = (base + 1 < n) ? cnt[base + 1] : 0;
    int v2 = (base + 2 < n) ? cnt[base + 2] : 0;
    int v3 = (base + 3 < n) ? cnt[base + 3] : 0;
    int s0 = v0, s1 = s0 + v1, s2 = s1 + v2, s3 = s2 + v3;
    int incl = s3;
    #pragma unroll
    for (int off = 1; off < 32; off <<= 1) {
        int t = __shfl_up_sync(0xffffffffu, incl, off);
        if (lane >= off) incl += t;
    }
    if (lane == 31) wsum[wid] = incl;
    __syncthreads();
    if (wid == 0) {
        int w = (lane < 8) ? wsum[lane] : 0;
        #pragma unroll
        for (int off = 1; off < 8; off <<= 1) {
            int t = __shfl_up_sync(0xffffffffu, w, off);
            if (lane >= off) w += t;
        }
        if (lane < 8) wsum[lane] = w;
    }
    __syncthreads();
    int woff = (wid > 0) ? wsum[wid - 1] : 0;
    int excl = incl - s3 + woff;
    if (base     < n) rowptr[base + 1] = excl + s0;
    if (base + 1 < n) rowptr[base + 2] = excl + s1;
    if (base + 2 < n) rowptr[base + 3] = excl + s2;
    if (base + 3 < n) rowptr[base + 4] = excl + s3;
    __syncthreads();
    if (tid == 255) bsum[blockIdx.x] = wsum[7];
}

// exclusive scan over block sums (<= 64 entries), single warp
__global__ void scan_bsum_kernel(int* bsum, int nb) {
    int lane = threadIdx.x;
    int carry = 0;
    for (int base = 0; base < nb; base += 32) {
        int v = (base + lane < nb) ? bsum[base + lane] : 0;
        int incl = v;
        #pragma unroll
        for (int off = 1; off < 32; off <<= 1) {
            int t = __shfl_up_sync(0xffffffffu, incl, off);
            if (lane >= off) incl += t;
        }
        int excl = incl - v + carry;
        if (base + lane < nb) bsum[base + lane] = excl;
        carry += __shfl_sync(0xffffffffu, incl, 31);
    }
}

__global__ void scan_add_kernel(const int* __restrict__ bsum, int* __restrict__ rowptr, int n) {
    int i = blockIdx.x * blockDim.x + threadIdx.x;
    if (i < n) rowptr[i + 1] += bsum[i >> 10];
    if (i == 0) rowptr[0] = 0;
}

__global__ void scatter_kernel(const int* __restrict__ src, const int* __restrict__ dst,
                               const int* __restrict__ rowptr, int* __restrict__ fill,
                               int* __restrict__ srcs, int e) {
    int i = blockIdx.x * blockDim.x + threadIdx.x;
    if (i < e) {
        int d = dst[i];
        int pos = rowptr[d] + atomicAdd(&fill[d], 1);
        srcs[pos] = src[i];
    }
}

// ------- register-tiled GEMM with packed FFMA2: F[n,M] = X[n,128] @ W -------
// Block: 256 threads = 8 warps; tile = 64 nodes x 128 cols.
// Lane owns 4 cols x 8 nodes; accumulators packed as f32x2 over node-pairs.
// X is staged transposed (k-major) in smem with a pair-granularity XOR swizzle
// so that node-pairs load via a single broadcast LDS.64.
// DUAL=true: cols 0-63 come from Wa -> outA, cols 64-127 from Wb -> outB
// (both 64-wide, row stride 64). DUAL=false: single 128-wide W/out.
template <bool DUAL>
__global__ __launch_bounds__(256) void gemm2_kernel(
    const float* __restrict__ X,
    const float* __restrict__ Wa, const float* __restrict__ Wb,
    float* __restrict__ outA, float* __restrict__ outB, int n)
{
    __shared__ float xs[128][64];    // [k][swizzled node]
    int tid = threadIdx.x;
    int n0 = blockIdx.x * 64;

    // ---- stage X transposed with swizzle ----
    #pragma unroll
    for (int it = 0; it < 8; it++) {
        int idx  = it * 256 + tid;
        int node = idx >> 5;          // 0..63 (same for whole warp)
        int kg   = idx & 31;          // float4 group of k (lane index)
        float4 v = make_float4(0.f, 0.f, 0.f, 0.f);
        if (n0 + node < n)
            v = reinterpret_cast<const float4*>(X)[(size_t)(n0 + node) * 32 + kg];
        int pos = 2 * ((node >> 1) ^ (kg & 15)) + (node & 1);
        xs[4 * kg + 0][pos] = v.x;
        xs[4 * kg + 1][pos] = v.y;
        xs[4 * kg + 2][pos] = v.z;
        xs[4 * kg + 3][pos] = v.w;
    }
    __syncthreads();

    int lane = tid & 31, w = tid >> 5;
    int pp0 = w * 4;                  // first absolute node-pair of this warp
    const float* Wp;
    int cl, half = 0;
    if (DUAL) { half = lane >> 4; cl = (lane & 15) * 4; Wp = half ? Wb : Wa; }
    else      { cl = lane * 4; Wp = Wa; }
    const int wstride = DUAL ? 64 : 128;

    unsigned long long acc[4][4];
    #pragma unroll
    for (int j = 0; j < 4; j++)
        #pragma unroll
        for (int p = 0; p < 4; p++) acc[j][p] = 0ull;

    #pragma unroll 2
    for (int k = 0; k < 128; k++) {
        float4 wv = *reinterpret_cast<const float4*>(Wp + k * wstride + cl);
        unsigned long long wd0 = pack2(wv.x, wv.x);
        unsigned long long wd1 = pack2(wv.y, wv.y);
        unsigned long long wd2 = pack2(wv.z, wv.z);
        unsigned long long wd3 = pack2(wv.w, wv.w);
        int f = (k >> 2) & 15;
        unsigned long long xp[4];
        #pragma unroll
        for (int p = 0; p < 4; p++)
            xp[p] = *reinterpret_cast<const unsigned long long*>(
                        &xs[k][2 * ((pp0 + p) ^ f)]);
        #pragma unroll
        for (int p = 0; p < 4; p++) {
            acc[0][p] = fma2(wd0, xp[p], acc[0][p]);
            acc[1][p] = fma2(wd1, xp[p], acc[1][p]);
            acc[2][p] = fma2(wd2, xp[p], acc[2][p]);
            acc[3][p] = fma2(wd3, xp[p], acc[3][p]);
        }
    }

    // ---- epilogue: unpack and store ----
    float* outp = DUAL ? (half ? outB : outA) : outA;
    const int ostride = DUAL ? 64 : 128;
    #pragma unroll
    for (int p = 0; p < 4; p++) {
        int ng = n0 + (pp0 + p) * 2;
        float a0, a1, a2, a3, b0, b1, b2, b3;
        unpack2(acc[0][p], a0, b0);
        unpack2(acc[1][p], a1, b1);
        unpack2(acc[2][p], a2, b2);
        unpack2(acc[3][p], a3, b3);
        if (ng < n)
            *reinterpret_cast<float4*>(outp + (size_t)ng * ostride + cl) =
                make_float4(a0, a1, a2, a3);
        if (ng + 1 < n)
            *reinterpret_cast<float4*>(outp + (size_t)(ng + 1) * ostride + cl) =
                make_float4(b0, b1, b2, b3);
    }
}

// ---------------- per-node attention logits: el/er ----------------
template <int H, int D>
__global__ void eler_kernel(const float* __restrict__ F, const float* __restrict__ al,
                            const float* __restrict__ ar, float* __restrict__ EL,
                            float* __restrict__ ER, int n) {
    int idx = blockIdx.x * blockDim.x + threadIdx.x;
    if (idx >= n * H) return;
    int node = idx / H, h = idx % H;
    const float* fr = F + node * H * D + h * D;
    const float* a  = al + h * D;
    const float* r  = ar + h * D;
    float el = 0.f, er = 0.f;
    #pragma unroll
    for (int d = 0; d < D; d += 4) {
        float4 fv = *reinterpret_cast<const float4*>(fr + d);
        float4 av = *reinterpret_cast<const float4*>(a + d);
        float4 rv = *reinterpret_cast<const float4*>(r + d);
        el += fv.x * av.x + fv.y * av.y + fv.z * av.z + fv.w * av.w;
        er += fv.x * rv.x + fv.y * rv.y + fv.z * rv.z + fv.w * rv.w;
    }
    EL[idx] = el;
    ER[idx] = er;
}

// ---------- fused edge softmax + aggregation + epilogue (warp/node) ---------
template <int H, int D, bool ELU_ACT, bool HAS_RES>
__global__ void fused_layer_kernel(const float* __restrict__ F,
                                   const float* __restrict__ EL,
                                   const float* __restrict__ ER,
                                   const int* __restrict__ rowptr,
                                   const int* __restrict__ srcs,
                                   const float* __restrict__ RESP,
                                   const float* __restrict__ B,
                                   float* __restrict__ OUT, int n) {
    constexpr int HD  = H * D;
    constexpr int VPL = HD / 32;     // 4 (HD=128) or 2 (HD=64)
    int gw = (blockIdx.x * blockDim.x + threadIdx.x) >> 5;
    if (gw >= n) return;
    int lane = threadIdx.x & 31;

    float er[H];
    #pragma unroll
    for (int h = 0; h < H; h++) er[h] = ER[gw * H + h];
    int beg = rowptr[gw], end = rowptr[gw + 1];

    // ---- pass A: denominator sum of exp(leaky(el+er)) per head (lane-strided)
    float sm[H];
    #pragma unroll
    for (int h = 0; h < H; h++) sm[h] = 0.f;
    for (int i = beg + lane; i < end; i += 32) {
        int s = srcs[i];
        if constexpr (H == 8) {
            float4 a = *reinterpret_cast<const float4*>(EL + s * 8);
            float4 b = *reinterpret_cast<const float4*>(EL + s * 8 + 4);
            float e[8] = {a.x, a.y, a.z, a.w, b.x, b.y, b.z, b.w};
            #pragma unroll
            for (int h = 0; h < 8; h++) {
                float x = e[h] + er[h];
                x = x > 0.f ? x : 0.2f * x;
                sm[h] += __expf(x);
            }
        } else {
            float x = EL[s] + er[0];
            x = x > 0.f ? x : 0.2f * x;
            sm[0] += __expf(x);
        }
    }
    #pragma unroll
    for (int h = 0; h < H; h++)
        #pragma unroll
        for (int o = 16; o; o >>= 1)
            sm[h] += __shfl_xor_sync(0xffffffffu, sm[h], o);

    // ---- pass B: weighted feature gather (whole warp walks each edge) ----
    constexpr int DSHIFT = (D == 16) ? 4 : 6;
    int col  = lane * VPL;
    int head = col >> DSHIFT;
    float sinv = 1.0f / sm[head];
    float erh  = er[head];
    float acc[VPL];
    #pragma unroll
    for (int j = 0; j < VPL; j++) acc[j] = 0.f;

    auto alpha_of = [&](int s) -> float {
        float x = EL[s * H + head] + erh;
        x = x > 0.f ? x : 0.2f * x;
        return __expf(x) * sinv;
    };

    int i = beg;
    for (; i + 4 <= end; i += 4) {
        int s0 = srcs[i], s1 = srcs[i + 1], s2 = srcs[i + 2], s3 = srcs[i + 3];
        float a0 = alpha_of(s0), a1 = alpha_of(s1), a2 = alpha_of(s2), a3 = alpha_of(s3);
        if constexpr (VPL == 4) {
            float4 v0 = *reinterpret_cast<const float4*>(F + s0 * HD + col);
            float4 v1 = *reinterpret_cast<const float4*>(F + s1 * HD + col);
            float4 v2 = *reinterpret_cast<const float4*>(F + s2 * HD + col);
            float4 v3 = *reinterpret_cast<const float4*>(F + s3 * HD + col);
            acc[0] += v0.x * a0 + v1.x * a1 + v2.x * a2 + v3.x * a3;
            acc[1] += v0.y * a0 + v1.y * a1 + v2.y * a2 + v3.y * a3;
            acc[2] += v0.z * a0 + v1.z * a1 + v2.z * a2 + v3.z * a3;
            acc[3] += v0.w * a0 + v1.w * a1 + v2.w * a2 + v3.w * a3;
        } else {
            float2 v0 = *reinterpret_cast<const float2*>(F + s0 * HD + col);
            float2 v1 = *reinterpret_cast<const float2*>(F + s1 * HD + col);
            float2 v2 = *reinterpret_cast<const float2*>(F + s2 * HD + col);
            float2 v3 = *reinterpret_cast<const float2*>(F + s3 * HD + col);
            acc[0] += v0.x * a0 + v1.x * a1 + v2.x * a2 + v3.x * a3;
            acc[1] += v0.y * a0 + v1.y * a1 + v2.y * a2 + v3.y * a3;
        }
    }
    for (; i < end; i++) {
        int s0 = srcs[i];
        float a0 = alpha_of(s0);
        if constexpr (VPL == 4) {
            float4 v0 = *reinterpret_cast<const float4*>(F + s0 * HD + col);
            acc[0] += v0.x * a0; acc[1] += v0.y * a0;
            acc[2] += v0.z * a0; acc[3] += v0.w * a0;
        } else {
            float2 v0 = *reinterpret_cast<const float2*>(F + s0 * HD + col);
            acc[0] += v0.x * a0; acc[1] += v0.y * a0;
        }
    }

    // ---- epilogue: + residual + bias, optional ELU ----
    float o[VPL];
    #pragma unroll
    for (int j = 0; j < VPL; j++) {
        float v = acc[j] + B[col + j];
        if constexpr (HAS_RES) v += RESP[gw * HD + col + j];
        if constexpr (ELU_ACT) v = v > 0.f ? v : expm1f(v);
        o[j] = v;
    }
    if constexpr (VPL == 4)
        *reinterpret_cast<float4*>(OUT + gw * HD + col) = make_float4(o[0], o[1], o[2], o[3]);
    else
        *reinterpret_cast<float2*>(OUT + gw * HD + col) = make_float2(o[0], o[1]);
}

// ---------------- launch ----------------
extern "C" void kernel_launch(void* const* d_in, const int* in_sizes, int n_in,
                              void* d_out, int out_size) {
    const float* x     = (const float*)d_in[0];
    const int*   src   = (const int*)d_in[1];
    const int*   dst   = (const int*)d_in[2];
    const float* W0    = (const float*)d_in[3];
    const float* al0   = (const float*)d_in[4];
    const float* ar0   = (const float*)d_in[5];
    const float* b0    = (const float*)d_in[6];
    const float* W1    = (const float*)d_in[7];
    const float* al1   = (const float*)d_in[8];
    const float* ar1   = (const float*)d_in[9];
    const float* b1    = (const float*)d_in[10];
    const float* W2    = (const float*)d_in[11];
    const float* al2   = (const float*)d_in[12];
    const float* ar2   = (const float*)d_in[13];
    const float* b2    = (const float*)d_in[14];
    const float* resW2 = (const float*)d_in[15];
    float* out = (float*)d_out;

    const int n = NN;
    const int e = in_sizes[1];

    void* p;
    cudaGetSymbolAddress(&p, g_f);      float* f_    = (float*)p;
    cudaGetSymbolAddress(&p, g_h1);     float* h1_   = (float*)p;
    cudaGetSymbolAddress(&p, g_h2);     float* h2_   = (float*)p;
    cudaGetSymbolAddress(&p, g_res2);   float* res2_ = (float*)p;
    cudaGetSymbolAddress(&p, g_el);     float* el_   = (float*)p;
    cudaGetSymbolAddress(&p, g_er);     float* er_   = (float*)p;
    cudaGetSymbolAddress(&p, g_cnt);    int*   cnt_  = (int*)p;
    cudaGetSymbolAddress(&p, g_rowptr); int*   rp_   = (int*)p;
    cudaGetSymbolAddress(&p, g_bsum);   int*   bs_   = (int*)p;
    cudaGetSymbolAddress(&p, g_srcs);   int*   srcs_ = (int*)p;

    const int TB = 256;
    int nb_n   = (n + TB - 1) / TB;
    int nb_e   = (e + TB - 1) / TB;
    int nb_w   = (n + 7) / 8;          // warp-per-node kernels, 8 warps/block
    int nb_nh  = (n * 8 + TB - 1) / TB;
    int nb_sc  = (n + 1023) / 1024;    // scan blocks
    int nb_g   = (n + 63) / 64;        // gemm blocks (64 nodes each)

    // ---- CSR build (sorted by dst) ----
    zero_int_kernel<<<nb_n, TB>>>(cnt_, n);
    hist_kernel<<<nb_e, TB>>>(dst, cnt_, e);
    scan_local_kernel<<<nb_sc, 256>>>(cnt_, rp_, bs_, n);
    scan_bsum_kernel<<<1, 32>>>(bs_, nb_sc);
    scan_add_kernel<<<nb_n, TB>>>(bs_, rp_, n);
    zero_int_kernel<<<nb_n, TB>>>(cnt_, n);
    scatter_kernel<<<nb_e, TB>>>(src, dst, rp_, cnt_, srcs_, e);

    // ---- layer 0: IN=128 -> 8x16, no residual, ELU ----
    gemm2_kernel<false><<<nb_g, 256>>>(x, W0, nullptr, f_, nullptr, n);
    eler_kernel<8, 16><<<nb_nh, TB>>>(f_, al0, ar0, el_, er_, n);
    fused_layer_kernel<8, 16, true, false><<<nb_w, TB>>>(f_, el_, er_, rp_, srcs_,
                                                         nullptr, b0, h1_, n);

    // ---- layer 1: 128 -> 8x16, identity residual, ELU ----
    gemm2_kernel<false><<<nb_g, 256>>>(h1_, W1, nullptr, f_, nullptr, n);
    eler_kernel<8, 16><<<nb_nh, TB>>>(f_, al1, ar1, el_, er_, n);
    fused_layer_kernel<8, 16, true, true><<<nb_w, TB>>>(f_, el_, er_, rp_, srcs_,
                                                        h1_, b1, h2_, n);

    // ---- layer 2: 128 -> 1x64 (+ linear residual GEMM fused), no act ----
    gemm2_kernel<true><<<nb_g, 256>>>(h2_, W2, resW2, f_, res2_, n);
    eler_kernel<1, 64><<<nb_n, TB>>>(f_, al2, ar2, el_, er_, n);
    fused_layer_kernel<1, 64, false, true><<<nb_w, TB>>>(f_, el_, er_, rp_, srcs_,
                                                         res2_, b2, out, n);
}

// round 7
// speedup vs baseline: 1.6131x; 1.0709x over previous
#include <cuda_runtime.h>
#include <math.h>

#define NN 50000
#define EE 1600000

// ---------------- device scratch (static: no allocs allowed) ----------------
__device__ float g_f[NN * 128];      // projected features of current layer
__device__ float g_h1[NN * 128];     // layer0 output / layer1 input+residual
__device__ float g_h2[NN * 128];     // layer1 output / layer2 input
__device__ float g_res2[NN * 64];    // linear residual for layer2
__device__ float g_el[NN * 8];
__device__ float g_er[NN * 8];
__device__ int   g_cnt[NN];
__device__ int   g_rowptr[NN + 1];
__device__ int   g_bsum[64];
__device__ int   g_srcs[EE];         // src node of each edge, sorted by dst

// ---------------- packed f32x2 helpers ----------------
__device__ __forceinline__ unsigned long long pack2(float lo, float hi) {
    unsigned long long r;
    asm("mov.b64 %0, {%1, %2};" : "=l"(r) : "f"(lo), "f"(hi));
    return r;
}
__device__ __forceinline__ void unpack2(unsigned long long v, float& lo, float& hi) {
    asm("mov.b64 {%0, %1}, %2;" : "=f"(lo), "=f"(hi) : "l"(v));
}
__device__ __forceinline__ unsigned long long fma2(unsigned long long a,
                                                   unsigned long long b,
                                                   unsigned long long c) {
    unsigned long long r;
    asm("fma.rn.f32x2 %0, %1, %2, %3;" : "=l"(r) : "l"(a), "l"(b), "l"(c));
    return r;
}

// ---------------- small utility kernels ----------------
__global__ void zero_int_kernel(int* p, int n) {
    int i = blockIdx.x * blockDim.x + threadIdx.x;
    if (i < n) p[i] = 0;
}

__global__ void hist_kernel(const int* __restrict__ dst, int* __restrict__ cnt, int e) {
    int i = blockIdx.x * blockDim.x + threadIdx.x;
    if (i < e) atomicAdd(&cnt[dst[i]], 1);
}

// -------- parallel scan: block-local (1024 elems/block) --------
__global__ void scan_local_kernel(const int* __restrict__ cnt, int* __restrict__ rowptr,
                                  int* __restrict__ bsum, int n) {
    __shared__ int wsum[8];
    int tid = threadIdx.x, lane = tid & 31, wid = tid >> 5;
    int base = blockIdx.x * 1024 + tid * 4;
    int v0 = (base     < n) ? cnt[base]     : 0;
    int v1 = (base + 1 < n) ? cnt[base + 1] : 0;
    int v2 = (base + 2 < n) ? cnt[base + 2] : 0;
    int v3 = (base + 3 < n) ? cnt[base + 3] : 0;
    int s0 = v0, s1 = s0 + v1, s2 = s1 + v2, s3 = s2 + v3;
    int incl = s3;
    #pragma unroll
    for (int off = 1; off < 32; off <<= 1) {
        int t = __shfl_up_sync(0xffffffffu, incl, off);
        if (lane >= off) incl += t;
    }
    if (lane == 31) wsum[wid] = incl;
    __syncthreads();
    if (wid == 0) {
        int w = (lane < 8) ? wsum[lane] : 0;
        #pragma unroll
        for (int off = 1; off < 8; off <<= 1) {
            int t = __shfl_up_sync(0xffffffffu, w, off);
            if (lane >= off) w += t;
        }
        if (lane < 8) wsum[lane] = w;
    }
    __syncthreads();
    int woff = (wid > 0) ? wsum[wid - 1] : 0;
    int excl = incl - s3 + woff;
    if (base     < n) rowptr[base + 1] = excl + s0;
    if (base + 1 < n) rowptr[base + 2] = excl + s1;
    if (base + 2 < n) rowptr[base + 3] = excl + s2;
    if (base + 3 < n) rowptr[base + 4] = excl + s3;
    __syncthreads();
    if (tid == 255) bsum[blockIdx.x] = wsum[7];
}

// exclusive scan over block sums (<= 64 entries), single warp
__global__ void scan_bsum_kernel(int* bsum, int nb) {
    int lane = threadIdx.x;
    int carry = 0;
    for (int base = 0; base < nb; base += 32) {
        int v = (base + lane < nb) ? bsum[base + lane] : 0;
        int incl = v;
        #pragma unroll
        for (int off = 1; off < 32; off <<= 1) {
            int t = __shfl_up_sync(0xffffffffu, incl, off);
            if (lane >= off) incl += t;
        }
        int excl = incl - v + carry;
        if (base + lane < nb) bsum[base + lane] = excl;
        carry += __shfl_sync(0xffffffffu, incl, 31);
    }
}

__global__ void scan_add_kernel(const int* __restrict__ bsum, int* __restrict__ rowptr, int n) {
    int i = blockIdx.x * blockDim.x + threadIdx.x;
    if (i < n) rowptr[i + 1] += bsum[i >> 10];
    if (i == 0) rowptr[0] = 0;
}

__global__ void scatter_kernel(const int* __restrict__ src, const int* __restrict__ dst,
                               const int* __restrict__ rowptr, int* __restrict__ fill,
                               int* __restrict__ srcs, int e) {
    int i = blockIdx.x * blockDim.x + threadIdx.x;
    if (i < e) {
        int d = dst[i];
        int pos = rowptr[d] + atomicAdd(&fill[d], 1);
        srcs[pos] = src[i];
    }
}

// ------- register-tiled GEMM with packed FFMA2: F[n,M] = X[n,128] @ W -------
template <bool DUAL>
__global__ __launch_bounds__(256) void gemm2_kernel(
    const float* __restrict__ X,
    const float* __restrict__ Wa, const float* __restrict__ Wb,
    float* __restrict__ outA, float* __restrict__ outB, int n)
{
    __shared__ float xs[128][64];    // [k][swizzled node]
    int tid = threadIdx.x;
    int n0 = blockIdx.x * 64;

    // ---- stage X transposed with swizzle ----
    #pragma unroll
    for (int it = 0; it < 8; it++) {
        int idx  = it * 256 + tid;
        int node = idx >> 5;          // 0..63 (same for whole warp)
        int kg   = idx & 31;          // float4 group of k (lane index)
        float4 v = make_float4(0.f, 0.f, 0.f, 0.f);
        if (n0 + node < n)
            v = reinterpret_cast<const float4*>(X)[(size_t)(n0 + node) * 32 + kg];
        int pos = 2 * ((node >> 1) ^ (kg & 15)) + (node & 1);
        xs[4 * kg + 0][pos] = v.x;
        xs[4 * kg + 1][pos] = v.y;
        xs[4 * kg + 2][pos] = v.z;
        xs[4 * kg + 3][pos] = v.w;
    }
    __syncthreads();

    int lane = tid & 31, w = tid >> 5;
    int pp0 = w * 4;                  // first absolute node-pair of this warp
    const float* Wp;
    int cl, half = 0;
    if (DUAL) { half = lane >> 4; cl = (lane & 15) * 4; Wp = half ? Wb : Wa; }
    else      { cl = lane * 4; Wp = Wa; }
    const int wstride = DUAL ? 64 : 128;

    unsigned long long acc[4][4];
    #pragma unroll
    for (int j = 0; j < 4; j++)
        #pragma unroll
        for (int p = 0; p < 4; p++) acc[j][p] = 0ull;

    #pragma unroll 2
    for (int k = 0; k < 128; k++) {
        float4 wv = *reinterpret_cast<const float4*>(Wp + k * wstride + cl);
        unsigned long long wd0 = pack2(wv.x, wv.x);
        unsigned long long wd1 = pack2(wv.y, wv.y);
        unsigned long long wd2 = pack2(wv.z, wv.z);
        unsigned long long wd3 = pack2(wv.w, wv.w);
        int f = (k >> 2) & 15;
        unsigned long long xp[4];
        #pragma unroll
        for (int p = 0; p < 4; p++)
            xp[p] = *reinterpret_cast<const unsigned long long*>(
                        &xs[k][2 * ((pp0 + p) ^ f)]);
        #pragma unroll
        for (int p = 0; p < 4; p++) {
            acc[0][p] = fma2(wd0, xp[p], acc[0][p]);
            acc[1][p] = fma2(wd1, xp[p], acc[1][p]);
            acc[2][p] = fma2(wd2, xp[p], acc[2][p]);
            acc[3][p] = fma2(wd3, xp[p], acc[3][p]);
        }
    }

    // ---- epilogue: unpack and store ----
    float* outp = DUAL ? (half ? outB : outA) : outA;
    const int ostride = DUAL ? 64 : 128;
    #pragma unroll
    for (int p = 0; p < 4; p++) {
        int ng = n0 + (pp0 + p) * 2;
        float a0, a1, a2, a3, b0, b1, b2, b3;
        unpack2(acc[0][p], a0, b0);
        unpack2(acc[1][p], a1, b1);
        unpack2(acc[2][p], a2, b2);
        unpack2(acc[3][p], a3, b3);
        if (ng < n)
            *reinterpret_cast<float4*>(outp + (size_t)ng * ostride + cl) =
                make_float4(a0, a1, a2, a3);
        if (ng + 1 < n)
            *reinterpret_cast<float4*>(outp + (size_t)(ng + 1) * ostride + cl) =
                make_float4(b0, b1, b2, b3);
    }
}

// ---------------- per-node attention logits: el/er ----------------
template <int H, int D>
__global__ void eler_kernel(const float* __restrict__ F, const float* __restrict__ al,
                            const float* __restrict__ ar, float* __restrict__ EL,
                            float* __restrict__ ER, int n) {
    int idx = blockIdx.x * blockDim.x + threadIdx.x;
    if (idx >= n * H) return;
    int node = idx / H, h = idx % H;
    const float* fr = F + node * H * D + h * D;
    const float* a  = al + h * D;
    const float* r  = ar + h * D;
    float el = 0.f, er = 0.f;
    #pragma unroll
    for (int d = 0; d < D; d += 4) {
        float4 fv = *reinterpret_cast<const float4*>(fr + d);
        float4 av = *reinterpret_cast<const float4*>(a + d);
        float4 rv = *reinterpret_cast<const float4*>(r + d);
        el += fv.x * av.x + fv.y * av.y + fv.z * av.z + fv.w * av.w;
        er += fv.x * rv.x + fv.y * rv.y + fv.z * rv.z + fv.w * rv.w;
    }
    EL[idx] = el;
    ER[idx] = er;
}

// ---- fused aggregation, SINGLE edge pass (deferred normalization) ----------
// acc = sum_e exp(leaky(el+er)) * f[src];  den accumulated alongside (every
// lane of a head group walks all edges, so den needs no warp reduction).
template <int H, int D, bool ELU_ACT, bool HAS_RES>
__global__ void fused_layer_kernel(const float* __restrict__ F,
                                   const float* __restrict__ EL,
                                   const float* __restrict__ ER,
                                   const int* __restrict__ rowptr,
                                   const int* __restrict__ srcs,
                                   const float* __restrict__ RESP,
                                   const float* __restrict__ B,
                                   float* __restrict__ OUT, int n) {
    constexpr int HD  = H * D;
    constexpr int VPL = HD / 32;     // 4 (HD=128) or 2 (HD=64)
    int gw = (blockIdx.x * blockDim.x + threadIdx.x) >> 5;
    if (gw >= n) return;
    int lane = threadIdx.x & 31;

    constexpr int DSHIFT = (D == 16) ? 4 : 6;
    int col  = lane * VPL;
    int head = col >> DSHIFT;
    float erh = ER[gw * H + head];
    int beg = rowptr[gw], end = rowptr[gw + 1];

    float den = 0.f;
    float acc[VPL];
    #pragma unroll
    for (int j = 0; j < VPL; j++) acc[j] = 0.f;

    auto w_of = [&](int s) -> float {
        float x = EL[s * H + head] + erh;
        x = x > 0.f ? x : 0.2f * x;
        return __expf(x);
    };

    int i = beg;
    for (; i + 4 <= end; i += 4) {
        int s0 = srcs[i], s1 = srcs[i + 1], s2 = srcs[i + 2], s3 = srcs[i + 3];
        float a0 = w_of(s0), a1 = w_of(s1), a2 = w_of(s2), a3 = w_of(s3);
        den += (a0 + a1) + (a2 + a3);
        if constexpr (VPL == 4) {
            float4 v0 = *reinterpret_cast<const float4*>(F + s0 * HD + col);
            float4 v1 = *reinterpret_cast<const float4*>(F + s1 * HD + col);
            float4 v2 = *reinterpret_cast<const float4*>(F + s2 * HD + col);
            float4 v3 = *reinterpret_cast<const float4*>(F + s3 * HD + col);
            acc[0] += v0.x * a0 + v1.x * a1 + v2.x * a2 + v3.x * a3;
            acc[1] += v0.y * a0 + v1.y * a1 + v2.y * a2 + v3.y * a3;
            acc[2] += v0.z * a0 + v1.z * a1 + v2.z * a2 + v3.z * a3;
            acc[3] += v0.w * a0 + v1.w * a1 + v2.w * a2 + v3.w * a3;
        } else {
            float2 v0 = *reinterpret_cast<const float2*>(F + s0 * HD + col);
            float2 v1 = *reinterpret_cast<const float2*>(F + s1 * HD + col);
            float2 v2 = *reinterpret_cast<const float2*>(F + s2 * HD + col);
            float2 v3 = *reinterpret_cast<const float2*>(F + s3 * HD + col);
            acc[0] += v0.x * a0 + v1.x * a1 + v2.x * a2 + v3.x * a3;
            acc[1] += v0.y * a0 + v1.y * a1 + v2.y * a2 + v3.y * a3;
        }
    }
    for (; i < end; i++) {
        int s0 = srcs[i];
        float a0 = w_of(s0);
        den += a0;
        if constexpr (VPL == 4) {
            float4 v0 = *reinterpret_cast<const float4*>(F + s0 * HD + col);
            acc[0] += v0.x * a0; acc[1] += v0.y * a0;
            acc[2] += v0.z * a0; acc[3] += v0.w * a0;
        } else {
            float2 v0 = *reinterpret_cast<const float2*>(F + s0 * HD + col);
            acc[0] += v0.x * a0; acc[1] += v0.y * a0;
        }
    }

    float sinv = (end > beg) ? 1.0f / den : 0.0f;

    // ---- epilogue: normalize + residual + bias, optional ELU ----
    float o[VPL];
    #pragma unroll
    for (int j = 0; j < VPL; j++) {
        float v = acc[j] * sinv + B[col + j];
        if constexpr (HAS_RES) v += RESP[gw * HD + col + j];
        if constexpr (ELU_ACT) v = v > 0.f ? v : expm1f(v);
        o[j] = v;
    }
    if constexpr (VPL == 4)
        *reinterpret_cast<float4*>(OUT + gw * HD + col) = make_float4(o[0], o[1], o[2], o[3]);
    else
        *reinterpret_cast<float2*>(OUT + gw * HD + col) = make_float2(o[0], o[1]);
}

// ---------------- launch ----------------
extern "C" void kernel_launch(void* const* d_in, const int* in_sizes, int n_in,
                              void* d_out, int out_size) {
    const float* x     = (const float*)d_in[0];
    const int*   src   = (const int*)d_in[1];
    const int*   dst   = (const int*)d_in[2];
    const float* W0    = (const float*)d_in[3];
    const float* al0   = (const float*)d_in[4];
    const float* ar0   = (const float*)d_in[5];
    const float* b0    = (const float*)d_in[6];
    const float* W1    = (const float*)d_in[7];
    const float* al1   = (const float*)d_in[8];
    const float* ar1   = (const float*)d_in[9];
    const float* b1    = (const float*)d_in[10];
    const float* W2    = (const float*)d_in[11];
    const float* al2   = (const float*)d_in[12];
    const float* ar2   = (const float*)d_in[13];
    const float* b2    = (const float*)d_in[14];
    const float* resW2 = (const float*)d_in[15];
    float* out = (float*)d_out;

    const int n = NN;
    const int e = in_sizes[1];

    void* p;
    cudaGetSymbolAddress(&p, g_f);      float* f_    = (float*)p;
    cudaGetSymbolAddress(&p, g_h1);     float* h1_   = (float*)p;
    cudaGetSymbolAddress(&p, g_h2);     float* h2_   = (float*)p;
    cudaGetSymbolAddress(&p, g_res2);   float* res2_ = (float*)p;
    cudaGetSymbolAddress(&p, g_el);     float* el_   = (float*)p;
    cudaGetSymbolAddress(&p, g_er);     float* er_   = (float*)p;
    cudaGetSymbolAddress(&p, g_cnt);    int*   cnt_  = (int*)p;
    cudaGetSymbolAddress(&p, g_rowptr); int*   rp_   = (int*)p;
    cudaGetSymbolAddress(&p, g_bsum);   int*   bs_   = (int*)p;
    cudaGetSymbolAddress(&p, g_srcs);   int*   srcs_ = (int*)p;

    const int TB = 256;
    int nb_n   = (n + TB - 1) / TB;
    int nb_e   = (e + TB - 1) / TB;
    int nb_w   = (n + 7) / 8;          // warp-per-node kernels, 8 warps/block
    int nb_nh  = (n * 8 + TB - 1) / TB;
    int nb_sc  = (n + 1023) / 1024;    // scan blocks
    int nb_g   = (n + 63) / 64;        // gemm blocks (64 nodes each)

    // ---- CSR build (sorted by dst) ----
    zero_int_kernel<<<nb_n, TB>>>(cnt_, n);
    hist_kernel<<<nb_e, TB>>>(dst, cnt_, e);
    scan_local_kernel<<<nb_sc, 256>>>(cnt_, rp_, bs_, n);
    scan_bsum_kernel<<<1, 32>>>(bs_, nb_sc);
    scan_add_kernel<<<nb_n, TB>>>(bs_, rp_, n);
    zero_int_kernel<<<nb_n, TB>>>(cnt_, n);
    scatter_kernel<<<nb_e, TB>>>(src, dst, rp_, cnt_, srcs_, e);

    // ---- layer 0: IN=128 -> 8x16, no residual, ELU ----
    gemm2_kernel<false><<<nb_g, 256>>>(x, W0, nullptr, f_, nullptr, n);
    eler_kernel<8, 16><<<nb_nh, TB>>>(f_, al0, ar0, el_, er_, n);
    fused_layer_kernel<8, 16, true, false><<<nb_w, TB>>>(f_, el_, er_, rp_, srcs_,
                                                         nullptr, b0, h1_, n);

    // ---- layer 1: 128 -> 8x16, identity residual, ELU ----
    gemm2_kernel<false><<<nb_g, 256>>>(h1_, W1, nullptr, f_, nullptr, n);
    eler_kernel<8, 16><<<nb_nh, TB>>>(f_, al1, ar1, el_, er_, n);
    fused_layer_kernel<8, 16, true, true><<<nb_w, TB>>>(f_, el_, er_, rp_, srcs_,
                                                        h1_, b1, h2_, n);

    // ---- layer 2: 128 -> 1x64 (+ linear residual GEMM fused), no act ----
    gemm2_kernel<true><<<nb_g, 256>>>(h2_, W2, resW2, f_, res2_, n);
    eler_kernel<1, 64><<<nb_n, TB>>>(f_, al2, ar2, el_, er_, n);
    fused_layer_kernel<1, 64, false, true><<<nb_w, TB>>>(f_, el_, er_, rp_, srcs_,
                                                         res2_, b2, out, n);
}

// round 12
// speedup vs baseline: 1.7326x; 1.0741x over previous
#include <cuda_runtime.h>
#include <cuda_fp16.h>
#include <math.h>

#define NN 50000
#define EE 1600000

// ---------------- device scratch (static: no allocs allowed) ----------------
__device__ float g_f[NN * 128];      // projected features f32 (for eler)
__device__ __half g_fb[NN * 128];    // fp16 copy of f (gather operand)
__device__ float g_h1[NN * 128];
__device__ float g_h2[NN * 128];
__device__ float g_res2[NN * 64];
__device__ float g_el[NN * 8];
__device__ float g_er[NN * 8];
__device__ int   g_cnt[NN];
__device__ int   g_rowptr[NN + 1];
__device__ int   g_bsum[64];
__device__ int   g_srcs[EE];

// ---------------- packed f32x2 helpers ----------------
__device__ __forceinline__ unsigned long long pack2(float lo, float hi) {
    unsigned long long r;
    asm("mov.b64 %0, {%1, %2};" : "=l"(r) : "f"(lo), "f"(hi));
    return r;
}
__device__ __forceinline__ void unpack2(unsigned long long v, float& lo, float& hi) {
    asm("mov.b64 {%0, %1}, %2;" : "=f"(lo), "=f"(hi) : "l"(v));
}
__device__ __forceinline__ unsigned long long fma2(unsigned long long a,
                                                   unsigned long long b,
                                                   unsigned long long c) {
    unsigned long long r;
    asm("fma.rn.f32x2 %0, %1, %2, %3;" : "=l"(r) : "l"(a), "l"(b), "l"(c));
    return r;
}

// ---------------- small utility kernels ----------------
__global__ void zero_int_kernel(int* p, int n) {
    int i = blockIdx.x * blockDim.x + threadIdx.x;
    if (i < n) p[i] = 0;
}

__global__ void hist_kernel(const int* __restrict__ dst, int* __restrict__ cnt, int e) {
    int i = blockIdx.x * blockDim.x + threadIdx.x;
    if (i < e) atomicAdd(&cnt[dst[i]], 1);
}

__global__ void scan_local_kernel(const int* __restrict__ cnt, int* __restrict__ rowptr,
                                  int* __restrict__ bsum, int n) {
    __shared__ int wsum[8];
    int tid = threadIdx.x, lane = tid & 31, wid = tid >> 5;
    int base = blockIdx.x * 1024 + tid * 4;
    int v0 = (base     < n) ? cnt[base]     : 0;
    int v1 = (base + 1 < n) ? cnt[base + 1] : 0;
    int v2 = (base + 2 < n) ? cnt[base + 2] : 0;
    int v3 = (base + 3 < n) ? cnt[base + 3] : 0;
    int s0 = v0, s1 = s0 + v1, s2 = s1 + v2, s3 = s2 + v3;
    int incl = s3;
    #pragma unroll
    for (int off = 1; off < 32; off <<= 1) {
        int t = __shfl_up_sync(0xffffffffu, incl, off);
        if (lane >= off) incl += t;
    }
    if (lane == 31) wsum[wid] = incl;
    __syncthreads();
    if (wid == 0) {
        int w = (lane < 8) ? wsum[lane] : 0;
        #pragma unroll
        for (int off = 1; off < 8; off <<= 1) {
            int t = __shfl_up_sync(0xffffffffu, w, off);
            if (lane >= off) w += t;
        }
        if (lane < 8) wsum[lane] = w;
    }
    __syncthreads();
    int woff = (wid > 0) ? wsum[wid - 1] : 0;
    int excl = incl - s3 + woff;
    if (base     < n) rowptr[base + 1] = excl + s0;
    if (base + 1 < n) rowptr[base + 2] = excl + s1;
    if (base + 2 < n) rowptr[base + 3] = excl + s2;
    if (base + 3 < n) rowptr[base + 4] = excl + s3;
    __syncthreads();
    if (tid == 255) bsum[blockIdx.x] = wsum[7];
}

__global__ void scan_bsum_kernel(int* bsum, int nb) {
    int lane = threadIdx.x;
    int carry = 0;
    for (int base = 0; base < nb; base += 32) {
        int v = (base + lane < nb) ? bsum[base + lane] : 0;
        int incl = v;
        #pragma unroll
        for (int off = 1; off < 32; off <<= 1) {
            int t = __shfl_up_sync(0xffffffffu, incl, off);
            if (lane >= off) incl += t;
        }
        int excl = incl - v + carry;
        if (base + lane < nb) bsum[base + lane] = excl;
        carry += __shfl_sync(0xffffffffu, incl, 31);
    }
}

__global__ void scan_add_kernel(const int* __restrict__ bsum, int* __restrict__ rowptr, int n) {
    int i = blockIdx.x * blockDim.x + threadIdx.x;
    if (i < n) rowptr[i + 1] += bsum[i >> 10];
    if (i == 0) rowptr[0] = 0;
}

__global__ void scatter_kernel(const int* __restrict__ src, const int* __restrict__ dst,
                               const int* __restrict__ rowptr, int* __restrict__ fill,
                               int* __restrict__ srcs, int e) {
    int i = blockIdx.x * blockDim.x + threadIdx.x;
    if (i < e) {
        int d = dst[i];
        int pos = rowptr[d] + atomicAdd(&fill[d], 1);
        srcs[pos] = src[i];
    }
}

// ------- register-tiled GEMM with packed FFMA2: F[n,M] = X[n,128] @ W -------
// Also emits an fp16 copy of the primary output (the gather operand).
template <bool DUAL>
__global__ __launch_bounds__(256) void gemm2_kernel(
    const float* __restrict__ X,
    const float* __restrict__ Wa, const float* __restrict__ Wb,
    float* __restrict__ outA, float* __restrict__ outB,
    __half* __restrict__ FB, int n)
{
    __shared__ float xs[128][64];    // [k][swizzled node]
    int tid = threadIdx.x;
    int n0 = blockIdx.x * 64;

    #pragma unroll
    for (int it = 0; it < 8; it++) {
        int idx  = it * 256 + tid;
        int node = idx >> 5;
        int kg   = idx & 31;
        float4 v = make_float4(0.f, 0.f, 0.f, 0.f);
        if (n0 + node < n)
            v = reinterpret_cast<const float4*>(X)[(size_t)(n0 + node) * 32 + kg];
        int pos = 2 * ((node >> 1) ^ (kg & 15)) + (node & 1);
        xs[4 * kg + 0][pos] = v.x;
        xs[4 * kg + 1][pos] = v.y;
        xs[4 * kg + 2][pos] = v.z;
        xs[4 * kg + 3][pos] = v.w;
    }
    __syncthreads();

    int lane = tid & 31, w = tid >> 5;
    int pp0 = w * 4;
    const float* Wp;
    int cl, half = 0;
    if (DUAL) { half = lane >> 4; cl = (lane & 15) * 4; Wp = half ? Wb : Wa; }
    else      { cl = lane * 4; Wp = Wa; }
    const int wstride = DUAL ? 64 : 128;

    unsigned long long acc[4][4];
    #pragma unroll
    for (int j = 0; j < 4; j++)
        #pragma unroll
        for (int p = 0; p < 4; p++) acc[j][p] = 0ull;

    #pragma unroll 2
    for (int k = 0; k < 128; k++) {
        float4 wv = *reinterpret_cast<const float4*>(Wp + k * wstride + cl);
        unsigned long long wd0 = pack2(wv.x, wv.x);
        unsigned long long wd1 = pack2(wv.y, wv.y);
        unsigned long long wd2 = pack2(wv.z, wv.z);
        unsigned long long wd3 = pack2(wv.w, wv.w);
        int f = (k >> 2) & 15;
        unsigned long long xp[4];
        #pragma unroll
        for (int p = 0; p < 4; p++)
            xp[p] = *reinterpret_cast<const unsigned long long*>(
                        &xs[k][2 * ((pp0 + p) ^ f)]);
        #pragma unroll
        for (int p = 0; p < 4; p++) {
            acc[0][p] = fma2(wd0, xp[p], acc[0][p]);
            acc[1][p] = fma2(wd1, xp[p], acc[1][p]);
            acc[2][p] = fma2(wd2, xp[p], acc[2][p]);
            acc[3][p] = fma2(wd3, xp[p], acc[3][p]);
        }
    }

    float* outp = DUAL ? (half ? outB : outA) : outA;
    const int ostride = DUAL ? 64 : 128;
    bool writeFH = (!DUAL) || (half == 0);
    #pragma unroll
    for (int p = 0; p < 4; p++) {
        int ng = n0 + (pp0 + p) * 2;
        float a0, a1, a2, a3, b0, b1, b2, b3;
        unpack2(acc[0][p], a0, b0);
        unpack2(acc[1][p], a1, b1);
        unpack2(acc[2][p], a2, b2);
        unpack2(acc[3][p], a3, b3);
        if (ng < n) {
            *reinterpret_cast<float4*>(outp + (size_t)ng * ostride + cl) =
                make_float4(a0, a1, a2, a3);
            if (writeFH) {
                __half2 q0 = __floats2half2_rn(a0, a1);
                __half2 q1 = __floats2half2_rn(a2, a3);
                uint2 pk = make_uint2(*reinterpret_cast<unsigned int*>(&q0),
                                      *reinterpret_cast<unsigned int*>(&q1));
                *reinterpret_cast<uint2*>(FB + (size_t)ng * ostride + cl) = pk;
            }
        }
        if (ng + 1 < n) {
            *reinterpret_cast<float4*>(outp + (size_t)(ng + 1) * ostride + cl) =
                make_float4(b0, b1, b2, b3);
            if (writeFH) {
                __half2 q0 = __floats2half2_rn(b0, b1);
                __half2 q1 = __floats2half2_rn(b2, b3);
                uint2 pk = make_uint2(*reinterpret_cast<unsigned int*>(&q0),
                                      *reinterpret_cast<unsigned int*>(&q1));
                *reinterpret_cast<uint2*>(FB + (size_t)(ng + 1) * ostride + cl) = pk;
            }
        }
    }
}

// ---------------- per-node attention logits: el/er ----------------
template <int H, int D>
__global__ void eler_kernel(const float* __restrict__ F, const float* __restrict__ al,
                            const float* __restrict__ ar, float* __restrict__ EL,
                            float* __restrict__ ER, int n) {
    int idx = blockIdx.x * blockDim.x + threadIdx.x;
    if (idx >= n * H) return;
    int node = idx / H, h = idx % H;
    const float* fr = F + node * H * D + h * D;
    const float* a  = al + h * D;
    const float* r  = ar + h * D;
    float el = 0.f, er = 0.f;
    #pragma unroll
    for (int d = 0; d < D; d += 4) {
        float4 fv = *reinterpret_cast<const float4*>(fr + d);
        float4 av = *reinterpret_cast<const float4*>(a + d);
        float4 rv = *reinterpret_cast<const float4*>(r + d);
        el += fv.x * av.x + fv.y * av.y + fv.z * av.z + fv.w * av.w;
        er += fv.x * rv.x + fv.y * rv.y + fv.z * rv.z + fv.w * rv.w;
    }
    EL[idx] = el;
    ER[idx] = er;
}

// ---- fused aggregation: single edge pass, fp16 gathers, unroll 8 -----------
template <int H, int D, bool ELU_ACT, bool HAS_RES>
__global__ void fused_layer_kernel(const __half* __restrict__ FB,
                                   const float* __restrict__ EL,
                                   const float* __restrict__ ER,
                                   const int* __restrict__ rowptr,
                                   const int* __restrict__ srcs,
                                   const float* __restrict__ RESP,
                                   const float* __restrict__ B,
                                   float* __restrict__ OUT, int n) {
    constexpr int HD  = H * D;
    constexpr int VPL = HD / 32;     // 4 (HD=128) or 2 (HD=64)
    int gw = (blockIdx.x * blockDim.x + threadIdx.x) >> 5;
    if (gw >= n) return;
    int lane = threadIdx.x & 31;

    constexpr int DSHIFT = (D == 16) ? 4 : 6;
    int col  = lane * VPL;
    int head = col >> DSHIFT;
    float erh = ER[gw * H + head];
    int beg = rowptr[gw], end = rowptr[gw + 1];

    float den = 0.f;
    float acc[VPL];
    #pragma unroll
    for (int j = 0; j < VPL; j++) acc[j] = 0.f;

    int i = beg;
    for (; i + 8 <= end; i += 8) {
        int s[8];
        #pragma unroll
        for (int u = 0; u < 8; u++) s[u] = srcs[i + u];
        float elv[8];
        #pragma unroll
        for (int u = 0; u < 8; u++) elv[u] = EL[s[u] * H + head];
        if constexpr (VPL == 4) {
            uint2 v[8];
            #pragma unroll
            for (int u = 0; u < 8; u++)
                v[u] = *reinterpret_cast<const uint2*>(FB + (size_t)s[u] * HD + col);
            #pragma unroll
            for (int u = 0; u < 8; u++) {
                float x = elv[u] + erh;
                x = x > 0.f ? x : 0.2f * x;
                float a = __expf(x);
                den += a;
                float2 f01 = __half22float2(*reinterpret_cast<__half2*>(&v[u].x));
                float2 f23 = __half22float2(*reinterpret_cast<__half2*>(&v[u].y));
                acc[0] += f01.x * a; acc[1] += f01.y * a;
                acc[2] += f23.x * a; acc[3] += f23.y * a;
            }
        } else {
            unsigned int v[8];
            #pragma unroll
            for (int u = 0; u < 8; u++)
                v[u] = *reinterpret_cast<const unsigned int*>(FB + (size_t)s[u] * HD + col);
            #pragma unroll
            for (int u = 0; u < 8; u++) {
                float x = elv[u] + erh;
                x = x > 0.f ? x : 0.2f * x;
                float a = __expf(x);
                den += a;
                float2 f01 = __half22float2(*reinterpret_cast<__half2*>(&v[u]));
                acc[0] += f01.x * a; acc[1] += f01.y * a;
            }
        }
    }
    for (; i < end; i++) {
        int s0 = srcs[i];
        float x = EL[s0 * H + head] + erh;
        x = x > 0.f ? x : 0.2f * x;
        float a = __expf(x);
        den += a;
        if constexpr (VPL == 4) {
            uint2 v = *reinterpret_cast<const uint2*>(FB + (size_t)s0 * HD + col);
            float2 f01 = __half22float2(*reinterpret_cast<__half2*>(&v.x));
            float2 f23 = __half22float2(*reinterpret_cast<__half2*>(&v.y));
            acc[0] += f01.x * a; acc[1] += f01.y * a;
            acc[2] += f23.x * a; acc[3] += f23.y * a;
        } else {
            unsigned int v = *reinterpret_cast<const unsigned int*>(FB + (size_t)s0 * HD + col);
            float2 f01 = __half22float2(*reinterpret_cast<__half2*>(&v));
            acc[0] += f01.x * a; acc[1] += f01.y * a;
        }
    }

    float sinv = (end > beg) ? 1.0f / den : 0.0f;

    float o[VPL];
    #pragma unroll
    for (int j = 0; j < VPL; j++) {
        float v = acc[j] * sinv + B[col + j];
        if constexpr (HAS_RES) v += RESP[gw * HD + col + j];
        if constexpr (ELU_ACT) v = v > 0.f ? v : expm1f(v);
        o[j] = v;
    }
    if constexpr (VPL == 4)
        *reinterpret_cast<float4*>(OUT + gw * HD + col) = make_float4(o[0], o[1], o[2], o[3]);
    else
        *reinterpret_cast<float2*>(OUT + gw * HD + col) = make_float2(o[0], o[1]);
}

// ---------------- launch ----------------
extern "C" void kernel_launch(void* const* d_in, const int* in_sizes, int n_in,
                              void* d_out, int out_size) {
    const float* x     = (const float*)d_in[0];
    const int*   src   = (const int*)d_in[1];
    const int*   dst   = (const int*)d_in[2];
    const float* W0    = (const float*)d_in[3];
    const float* al0   = (const float*)d_in[4];
    const float* ar0   = (const float*)d_in[5];
    const float* b0    = (const float*)d_in[6];
    const float* W1    = (const float*)d_in[7];
    const float* al1   = (const float*)d_in[8];
    const float* ar1   = (const float*)d_in[9];
    const float* b1    = (const float*)d_in[10];
    const float* W2    = (const float*)d_in[11];
    const float* al2   = (const float*)d_in[12];
    const float* ar2   = (const float*)d_in[13];
    const float* b2    = (const float*)d_in[14];
    const float* resW2 = (const float*)d_in[15];
    float* out = (float*)d_out;

    const int n = NN;
    const int e = in_sizes[1];

    void* p;
    cudaGetSymbolAddress(&p, g_f);      float* f_    = (float*)p;
    cudaGetSymbolAddress(&p, g_fb);     __half* fb_  = (__half*)p;
    cudaGetSymbolAddress(&p, g_h1);     float* h1_   = (float*)p;
    cudaGetSymbolAddress(&p, g_h2);     float* h2_   = (float*)p;
    cudaGetSymbolAddress(&p, g_res2);   float* res2_ = (float*)p;
    cudaGetSymbolAddress(&p, g_el);     float* el_   = (float*)p;
    cudaGetSymbolAddress(&p, g_er);     float* er_   = (float*)p;
    cudaGetSymbolAddress(&p, g_cnt);    int*   cnt_  = (int*)p;
    cudaGetSymbolAddress(&p, g_rowptr); int*   rp_   = (int*)p;
    cudaGetSymbolAddress(&p, g_bsum);   int*   bs_   = (int*)p;
    cudaGetSymbolAddress(&p, g_srcs);   int*   srcs_ = (int*)p;

    const int TB = 256;
    int nb_n   = (n + TB - 1) / TB;
    int nb_e   = (e + TB - 1) / TB;
    int nb_w   = (n + 7) / 8;
    int nb_nh  = (n * 8 + TB - 1) / TB;
    int nb_sc  = (n + 1023) / 1024;
    int nb_g   = (n + 63) / 64;

    // ---- CSR build (sorted by dst) ----
    zero_int_kernel<<<nb_n, TB>>>(cnt_, n);
    hist_kernel<<<nb_e, TB>>>(dst, cnt_, e);
    scan_local_kernel<<<nb_sc, 256>>>(cnt_, rp_, bs_, n);
    scan_bsum_kernel<<<1, 32>>>(bs_, nb_sc);
    scan_add_kernel<<<nb_n, TB>>>(bs_, rp_, n);
    zero_int_kernel<<<nb_n, TB>>>(cnt_, n);
    scatter_kernel<<<nb_e, TB>>>(src, dst, rp_, cnt_, srcs_, e);

    // ---- layer 0: IN=128 -> 8x16, no residual, ELU ----
    gemm2_kernel<false><<<nb_g, 256>>>(x, W0, nullptr, f_, nullptr, fb_, n);
    eler_kernel<8, 16><<<nb_nh, TB>>>(f_, al0, ar0, el_, er_, n);
    fused_layer_kernel<8, 16, true, false><<<nb_w, TB>>>(fb_, el_, er_, rp_, srcs_,
                                                         nullptr, b0, h1_, n);

    // ---- layer 1: 128 -> 8x16, identity residual, ELU ----
    gemm2_kernel<false><<<nb_g, 256>>>(h1_, W1, nullptr, f_, nullptr, fb_, n);
    eler_kernel<8, 16><<<nb_nh, TB>>>(f_, al1, ar1, el_, er_, n);
    fused_layer_kernel<8, 16, true, true><<<nb_w, TB>>>(fb_, el_, er_, rp_, srcs_,
                                                        h1_, b1, h2_, n);

    // ---- layer 2: 128 -> 1x64 (+ linear residual GEMM fused), no act ----
    gemm2_kernel<true><<<nb_g, 256>>>(h2_, W2, resW2, f_, res2_, fb_, n);
    eler_kernel<1, 64><<<nb_n, TB>>>(f_, al2, ar2, el_, er_, n);
    fused_layer_kernel<1, 64, false, true><<<nb_w, TB>>>(fb_, el_, er_, rp_, srcs_,
                                                         res2_, b2, out, n);
}

// round 13
// speedup vs baseline: 1.9247x; 1.1109x over previous
#include <cuda_runtime.h>
#include <cuda_fp16.h>
#include <math.h>

#define NN 50000
#define EE 1600000

// ---------------- device scratch (static: no allocs allowed) ----------------
__device__ __half g_fb[NN * 128];    // fp16 projected features (gather operand)
__device__ float g_h1[NN * 128];
__device__ float g_h2[NN * 128];
__device__ float g_res2[NN * 64];
__device__ float g_el[NN * 8];
__device__ float g_er[NN * 8];
__device__ int   g_cnt[NN];
__device__ int   g_rowptr[NN + 1];
__device__ int   g_bsum[64];
__device__ int   g_srcs[EE];

// ---------------- packed f32x2 helpers ----------------
__device__ __forceinline__ unsigned long long pack2(float lo, float hi) {
    unsigned long long r;
    asm("mov.b64 %0, {%1, %2};" : "=l"(r) : "f"(lo), "f"(hi));
    return r;
}
__device__ __forceinline__ void unpack2(unsigned long long v, float& lo, float& hi) {
    asm("mov.b64 {%0, %1}, %2;" : "=f"(lo), "=f"(hi) : "l"(v));
}
__device__ __forceinline__ unsigned long long fma2(unsigned long long a,
                                                   unsigned long long b,
                                                   unsigned long long c) {
    unsigned long long r;
    asm("fma.rn.f32x2 %0, %1, %2, %3;" : "=l"(r) : "l"(a), "l"(b), "l"(c));
    return r;
}
__device__ __forceinline__ unsigned long long add2(unsigned long long a,
                                                   unsigned long long b) {
    unsigned long long r;
    asm("add.rn.f32x2 %0, %1, %2;" : "=l"(r) : "l"(a), "l"(b));
    return r;
}

// ---------------- small utility kernels ----------------
__global__ void zero_int_kernel(int* p, int n) {
    int i = blockIdx.x * blockDim.x + threadIdx.x;
    if (i < n) p[i] = 0;
}

__global__ void hist_kernel(const int* __restrict__ dst, int* __restrict__ cnt, int e) {
    int i = blockIdx.x * blockDim.x + threadIdx.x;
    if (i < e) atomicAdd(&cnt[dst[i]], 1);
}

__global__ void scan_local_kernel(const int* __restrict__ cnt, int* __restrict__ rowptr,
                                  int* __restrict__ bsum, int n) {
    __shared__ int wsum[8];
    int tid = threadIdx.x, lane = tid & 31, wid = tid >> 5;
    int base = blockIdx.x * 1024 + tid * 4;
    int v0 = (base     < n) ? cnt[base]     : 0;
    int v1 = (base + 1 < n) ? cnt[base + 1] : 0;
    int v2 = (base + 2 < n) ? cnt[base + 2] : 0;
    int v3 = (base + 3 < n) ? cnt[base + 3] : 0;
    int s0 = v0, s1 = s0 + v1, s2 = s1 + v2, s3 = s2 + v3;
    int incl = s3;
    #pragma unroll
    for (int off = 1; off < 32; off <<= 1) {
        int t = __shfl_up_sync(0xffffffffu, incl, off);
        if (lane >= off) incl += t;
    }
    if (lane == 31) wsum[wid] = incl;
    __syncthreads();
    if (wid == 0) {
        int w = (lane < 8) ? wsum[lane] : 0;
        #pragma unroll
        for (int off = 1; off < 8; off <<= 1) {
            int t = __shfl_up_sync(0xffffffffu, w, off);
            if (lane >= off) w += t;
        }
        if (lane < 8) wsum[lane] = w;
    }
    __syncthreads();
    int woff = (wid > 0) ? wsum[wid - 1] : 0;
    int excl = incl - s3 + woff;
    if (base     < n) rowptr[base + 1] = excl + s0;
    if (base + 1 < n) rowptr[base + 2] = excl + s1;
    if (base + 2 < n) rowptr[base + 3] = excl + s2;
    if (base + 3 < n) rowptr[base + 4] = excl + s3;
    __syncthreads();
    if (tid == 255) bsum[blockIdx.x] = wsum[7];
}

__global__ void scan_bsum_kernel(int* bsum, int nb) {
    int lane = threadIdx.x;
    int carry = 0;
    for (int base = 0; base < nb; base += 32) {
        int v = (base + lane < nb) ? bsum[base + lane] : 0;
        int incl = v;
        #pragma unroll
        for (int off = 1; off < 32; off <<= 1) {
            int t = __shfl_up_sync(0xffffffffu, incl, off);
            if (lane >= off) incl += t;
        }
        int excl = incl - v + carry;
        if (base + lane < nb) bsum[base + lane] = excl;
        carry += __shfl_sync(0xffffffffu, incl, 31);
    }
}

__global__ void scan_add_kernel(const int* __restrict__ bsum, int* __restrict__ rowptr, int n) {
    int i = blockIdx.x * blockDim.x + threadIdx.x;
    if (i < n) rowptr[i + 1] += bsum[i >> 10];
    if (i == 0) rowptr[0] = 0;
}

__global__ void scatter_kernel(const int* __restrict__ src, const int* __restrict__ dst,
                               const int* __restrict__ rowptr, int* __restrict__ fill,
                               int* __restrict__ srcs, int e) {
    int i = blockIdx.x * blockDim.x + threadIdx.x;
    if (i < e) {
        int d = dst[i];
        int pos = rowptr[d] + atomicAdd(&fill[d], 1);
        srcs[pos] = src[i];
    }
}

// ------- register-tiled GEMM with packed FFMA2 + fused el/er epilogue -------
// Output: fp16 FB (gather operand) + EL/ER attention logits (f32, computed
// from f32 accumulators in-register). No f32 feature store for the primary
// output. DUAL: half 0 = W2 -> FB + EL/ER; half 1 = resW2 -> f32 outB.
template <bool DUAL>
__global__ __launch_bounds__(256) void gemm2_kernel(
    const float* __restrict__ X,
    const float* __restrict__ Wa, const float* __restrict__ Wb,
    const float* __restrict__ AL, const float* __restrict__ AR,
    float* __restrict__ outB,
    float* __restrict__ EL, float* __restrict__ ER,
    __half* __restrict__ FB, int n)
{
    __shared__ float xs[128][64];    // [k][swizzled node]
    int tid = threadIdx.x;
    int n0 = blockIdx.x * 64;

    #pragma unroll
    for (int it = 0; it < 8; it++) {
        int idx  = it * 256 + tid;
        int node = idx >> 5;
        int kg   = idx & 31;
        float4 v = make_float4(0.f, 0.f, 0.f, 0.f);
        if (n0 + node < n)
            v = reinterpret_cast<const float4*>(X)[(size_t)(n0 + node) * 32 + kg];
        int pos = 2 * ((node >> 1) ^ (kg & 15)) + (node & 1);
        xs[4 * kg + 0][pos] = v.x;
        xs[4 * kg + 1][pos] = v.y;
        xs[4 * kg + 2][pos] = v.z;
        xs[4 * kg + 3][pos] = v.w;
    }
    __syncthreads();

    int lane = tid & 31, w = tid >> 5;
    int pp0 = w * 4;
    const float* Wp;
    int cl, half = 0;
    if (DUAL) { half = lane >> 4; cl = (lane & 15) * 4; Wp = half ? Wb : Wa; }
    else      { cl = lane * 4; Wp = Wa; }
    const int wstride = DUAL ? 64 : 128;

    unsigned long long acc[4][4];
    #pragma unroll
    for (int j = 0; j < 4; j++)
        #pragma unroll
        for (int p = 0; p < 4; p++) acc[j][p] = 0ull;

    #pragma unroll 2
    for (int k = 0; k < 128; k++) {
        float4 wv = *reinterpret_cast<const float4*>(Wp + k * wstride + cl);
        unsigned long long wd0 = pack2(wv.x, wv.x);
        unsigned long long wd1 = pack2(wv.y, wv.y);
        unsigned long long wd2 = pack2(wv.z, wv.z);
        unsigned long long wd3 = pack2(wv.w, wv.w);
        int f = (k >> 2) & 15;
        unsigned long long xp[4];
        #pragma unroll
        for (int p = 0; p < 4; p++)
            xp[p] = *reinterpret_cast<const unsigned long long*>(
                        &xs[k][2 * ((pp0 + p) ^ f)]);
        #pragma unroll
        for (int p = 0; p < 4; p++) {
            acc[0][p] = fma2(wd0, xp[p], acc[0][p]);
            acc[1][p] = fma2(wd1, xp[p], acc[1][p]);
            acc[2][p] = fma2(wd2, xp[p], acc[2][p]);
            acc[3][p] = fma2(wd3, xp[p], acc[3][p]);
        }
    }

    // ---- fused el/er: per-head dot products from f32 accumulators ----
    unsigned long long elp[4], erp[4];
    #pragma unroll
    for (int p = 0; p < 4; p++) { elp[p] = 0ull; erp[p] = 0ull; }
    #pragma unroll
    for (int j = 0; j < 4; j++) {
        float a = AL[cl + j], r = AR[cl + j];
        unsigned long long ad = pack2(a, a), rd = pack2(r, r);
        #pragma unroll
        for (int p = 0; p < 4; p++) {
            elp[p] = fma2(ad, acc[j][p], elp[p]);
            erp[p] = fma2(rd, acc[j][p], erp[p]);
        }
    }
    // butterfly reduce within head group: 4 lanes (!DUAL, D=16) or 16 (DUAL)
    constexpr int REDMAX = DUAL ? 8 : 2;
    #pragma unroll
    for (int off = 1; off <= REDMAX; off <<= 1) {
        #pragma unroll
        for (int p = 0; p < 4; p++) {
            elp[p] = add2(elp[p], __shfl_xor_sync(0xffffffffu, elp[p], off));
            erp[p] = add2(erp[p], __shfl_xor_sync(0xffffffffu, erp[p], off));
        }
    }
    if ((!DUAL && (lane & 3) == 0) || (DUAL && lane == 0)) {
        int head = DUAL ? 0 : (cl >> 4);
        constexpr int HH = DUAL ? 1 : 8;
        #pragma unroll
        for (int p = 0; p < 4; p++) {
            int ng = n0 + (pp0 + p) * 2;
            float e0, e1, r0, r1;
            unpack2(elp[p], e0, e1);
            unpack2(erp[p], r0, r1);
            if (ng < n)     { EL[ng * HH + head] = e0; ER[ng * HH + head] = r0; }
            if (ng + 1 < n) { EL[(ng + 1) * HH + head] = e1; ER[(ng + 1) * HH + head] = r1; }
        }
    }

    // ---- stores: fp16 FB (primary) / f32 outB (DUAL residual half) ----
    const int ostride = DUAL ? 64 : 128;
    bool writeFH = (!DUAL) || (half == 0);
    #pragma unroll
    for (int p = 0; p < 4; p++) {
        int ng = n0 + (pp0 + p) * 2;
        float a0, a1, a2, a3, b0, b1, b2, b3;
        unpack2(acc[0][p], a0, b0);
        unpack2(acc[1][p], a1, b1);
        unpack2(acc[2][p], a2, b2);
        unpack2(acc[3][p], a3, b3);
        if (ng < n) {
            if (writeFH) {
                __half2 q0 = __floats2half2_rn(a0, a1);
                __half2 q1 = __floats2half2_rn(a2, a3);
                uint2 pk = make_uint2(*reinterpret_cast<unsigned int*>(&q0),
                                      *reinterpret_cast<unsigned int*>(&q1));
                *reinterpret_cast<uint2*>(FB + (size_t)ng * ostride + cl) = pk;
            } else {
                *reinterpret_cast<float4*>(outB + (size_t)ng * ostride + cl) =
                    make_float4(a0, a1, a2, a3);
            }
        }
        if (ng + 1 < n) {
            if (writeFH) {
                __half2 q0 = __floats2half2_rn(b0, b1);
                __half2 q1 = __floats2half2_rn(b2, b3);
                uint2 pk = make_uint2(*reinterpret_cast<unsigned int*>(&q0),
                                      *reinterpret_cast<unsigned int*>(&q1));
                *reinterpret_cast<uint2*>(FB + (size_t)(ng + 1) * ostride + cl) = pk;
            } else {
                *reinterpret_cast<float4*>(outB + (size_t)(ng + 1) * ostride + cl) =
                    make_float4(b0, b1, b2, b3);
            }
        }
    }
}

// ---- fused aggregation: single edge pass, fp16 gathers, srcs prefetch ------
template <int H, int D, bool ELU_ACT, bool HAS_RES>
__global__ void fused_layer_kernel(const __half* __restrict__ FB,
                                   const float* __restrict__ EL,
                                   const float* __restrict__ ER,
                                   const int* __restrict__ rowptr,
                                   const int* __restrict__ srcs,
                                   const float* __restrict__ RESP,
                                   const float* __restrict__ B,
                                   float* __restrict__ OUT, int n) {
    constexpr int HD  = H * D;
    constexpr int VPL = HD / 32;     // 4 (HD=128) or 2 (HD=64)
    int gw = (blockIdx.x * blockDim.x + threadIdx.x) >> 5;
    if (gw >= n) return;
    int lane = threadIdx.x & 31;

    constexpr int DSHIFT = (D == 16) ? 4 : 6;
    int col  = lane * VPL;
    int head = col >> DSHIFT;
    float erh = ER[gw * H + head];
    int beg = rowptr[gw], end = rowptr[gw + 1];

    float den = 0.f;
    float acc[VPL];
    #pragma unroll
    for (int j = 0; j < VPL; j++) acc[j] = 0.f;

    int i = beg;
    if (i + 8 <= end) {
        int s[8];
        #pragma unroll
        for (int u = 0; u < 8; u++) s[u] = srcs[i + u];
        while (true) {
            int ni = i + 8;
            bool haveN = (ni + 8 <= end);
            int sn[8];
            if (haveN) {
                #pragma unroll
                for (int u = 0; u < 8; u++) sn[u] = srcs[ni + u];
            }
            float elv[8];
            #pragma unroll
            for (int u = 0; u < 8; u++) elv[u] = EL[s[u] * H + head];
            if constexpr (VPL == 4) {
                uint2 v[8];
                #pragma unroll
                for (int u = 0; u < 8; u++)
                    v[u] = *reinterpret_cast<const uint2*>(FB + (size_t)s[u] * HD + col);
                #pragma unroll
                for (int u = 0; u < 8; u++) {
                    float x = elv[u] + erh;
                    x = x > 0.f ? x : 0.2f * x;
                    float a = __expf(x);
                    den += a;
                    float2 f01 = __half22float2(*reinterpret_cast<__half2*>(&v[u].x));
                    float2 f23 = __half22float2(*reinterpret_cast<__half2*>(&v[u].y));
                    acc[0] += f01.x * a; acc[1] += f01.y * a;
                    acc[2] += f23.x * a; acc[3] += f23.y * a;
                }
            } else {
                unsigned int v[8];
                #pragma unroll
                for (int u = 0; u < 8; u++)
                    v[u] = *reinterpret_cast<const unsigned int*>(FB + (size_t)s[u] * HD + col);
                #pragma unroll
                for (int u = 0; u < 8; u++) {
                    float x = elv[u] + erh;
                    x = x > 0.f ? x : 0.2f * x;
                    float a = __expf(x);
                    den += a;
                    float2 f01 = __half22float2(*reinterpret_cast<__half2*>(&v[u]));
                    acc[0] += f01.x * a; acc[1] += f01.y * a;
                }
            }
            i = ni;
            if (!haveN) break;
            #pragma unroll
            for (int u = 0; u < 8; u++) s[u] = sn[u];
        }
    }
    for (; i < end; i++) {
        int s0 = srcs[i];
        float x = EL[s0 * H + head] + erh;
        x = x > 0.f ? x : 0.2f * x;
        float a = __expf(x);
        den += a;
        if constexpr (VPL == 4) {
            uint2 v = *reinterpret_cast<const uint2*>(FB + (size_t)s0 * HD + col);
            float2 f01 = __half22float2(*reinterpret_cast<__half2*>(&v.x));
            float2 f23 = __half22float2(*reinterpret_cast<__half2*>(&v.y));
            acc[0] += f01.x * a; acc[1] += f01.y * a;
            acc[2] += f23.x * a; acc[3] += f23.y * a;
        } else {
            unsigned int v = *reinterpret_cast<const unsigned int*>(FB + (size_t)s0 * HD + col);
            float2 f01 = __half22float2(*reinterpret_cast<__half2*>(&v));
            acc[0] += f01.x * a; acc[1] += f01.y * a;
        }
    }

    float sinv = (end > beg) ? 1.0f / den : 0.0f;

    float o[VPL];
    #pragma unroll
    for (int j = 0; j < VPL; j++) {
        float v = acc[j] * sinv + B[col + j];
        if constexpr (HAS_RES) v += RESP[gw * HD + col + j];
        if constexpr (ELU_ACT) v = v > 0.f ? v : expm1f(v);
        o[j] = v;
    }
    if constexpr (VPL == 4)
        *reinterpret_cast<float4*>(OUT + gw * HD + col) = make_float4(o[0], o[1], o[2], o[3]);
    else
        *reinterpret_cast<float2*>(OUT + gw * HD + col) = make_float2(o[0], o[1]);
}

// ---------------- launch ----------------
extern "C" void kernel_launch(void* const* d_in, const int* in_sizes, int n_in,
                              void* d_out, int out_size) {
    const float* x     = (const float*)d_in[0];
    const int*   src   = (const int*)d_in[1];
    const int*   dst   = (const int*)d_in[2];
    const float* W0    = (const float*)d_in[3];
    const float* al0   = (const float*)d_in[4];
    const float* ar0   = (const float*)d_in[5];
    const float* b0    = (const float*)d_in[6];
    const float* W1    = (const float*)d_in[7];
    const float* al1   = (const float*)d_in[8];
    const float* ar1   = (const float*)d_in[9];
    const float* b1    = (const float*)d_in[10];
    const float* W2    = (const float*)d_in[11];
    const float* al2   = (const float*)d_in[12];
    const float* ar2   = (const float*)d_in[13];
    const float* b2    = (const float*)d_in[14];
    const float* resW2 = (const float*)d_in[15];
    float* out = (float*)d_out;

    const int n = NN;
    const int e = in_sizes[1];

    void* p;
    cudaGetSymbolAddress(&p, g_fb);     __half* fb_  = (__half*)p;
    cudaGetSymbolAddress(&p, g_h1);     float* h1_   = (float*)p;
    cudaGetSymbolAddress(&p, g_h2);     float* h2_   = (float*)p;
    cudaGetSymbolAddress(&p, g_res2);   float* res2_ = (float*)p;
    cudaGetSymbolAddress(&p, g_el);     float* el_   = (float*)p;
    cudaGetSymbolAddress(&p, g_er);     float* er_   = (float*)p;
    cudaGetSymbolAddress(&p, g_cnt);    int*   cnt_  = (int*)p;
    cudaGetSymbolAddress(&p, g_rowptr); int*   rp_   = (int*)p;
    cudaGetSymbolAddress(&p, g_bsum);   int*   bs_   = (int*)p;
    cudaGetSymbolAddress(&p, g_srcs);   int*   srcs_ = (int*)p;

    const int TB = 256;
    int nb_n   = (n + TB - 1) / TB;
    int nb_e   = (e + TB - 1) / TB;
    int nb_w   = (n + 7) / 8;
    int nb_sc  = (n + 1023) / 1024;
    int nb_g   = (n + 63) / 64;

    // ---- CSR build (sorted by dst) ----
    zero_int_kernel<<<nb_n, TB>>>(cnt_, n);
    hist_kernel<<<nb_e, TB>>>(dst, cnt_, e);
    scan_local_kernel<<<nb_sc, 256>>>(cnt_, rp_, bs_, n);
    scan_bsum_kernel<<<1, 32>>>(bs_, nb_sc);
    scan_add_kernel<<<nb_n, TB>>>(bs_, rp_, n);
    zero_int_kernel<<<nb_n, TB>>>(cnt_, n);
    scatter_kernel<<<nb_e, TB>>>(src, dst, rp_, cnt_, srcs_, e);

    // ---- layer 0: IN=128 -> 8x16, no residual, ELU ----
    gemm2_kernel<false><<<nb_g, 256>>>(x, W0, nullptr, al0, ar0,
                                       nullptr, el_, er_, fb_, n);
    fused_layer_kernel<8, 16, true, false><<<nb_w, TB>>>(fb_, el_, er_, rp_, srcs_,
                                                         nullptr, b0, h1_, n);

    // ---- layer 1: 128 -> 8x16, identity residual, ELU ----
    gemm2_kernel<false><<<nb_g, 256>>>(h1_, W1, nullptr, al1, ar1,
                                       nullptr, el_, er_, fb_, n);
    fused_layer_kernel<8, 16, true, true><<<nb_w, TB>>>(fb_, el_, er_, rp_, srcs_,
                                                        h1_, b1, h2_, n);

    // ---- layer 2: 128 -> 1x64 (+ linear residual GEMM fused), no act ----
    gemm2_kernel<true><<<nb_g, 256>>>(h2_, W2, resW2, al2, ar2,
                                      res2_, el_, er_, fb_, n);
    fused_layer_kernel<1, 64, false, true><<<nb_w, TB>>>(fb_, el_, er_, rp_, srcs_,
                                                         res2_, b2, out, n);
}